// round 1
// baseline (speedup 1.0000x reference)
#include <cuda_runtime.h>
#include <math.h>

// Problem constants
#define B_   4
#define S_   1024
#define D_   1024
#define H_   16
#define DK_  64

// GEMM tiling (C[M,N] = A[M,K] @ W[N,K]^T + bias)
#define GM   4096   // B_*S_
#define GN   1024
#define GK   1024
#define BM_  128
#define BN_  128
#define BK_  8
#define TM_  8
#define TN_  8

// Attention tiling
#define BQ   64
#define BKT  64
#define LDS  68     // smem row stride (floats), keeps float4 alignment, avoids bank conflicts
#define ATTN_SMEM (3 * 64 * LDS * 4)

// Scratch (allocation-free rule: __device__ globals)
__device__ float g_q[B_ * H_ * S_ * DK_];
__device__ float g_k[B_ * H_ * S_ * DK_];
__device__ float g_v[B_ * H_ * S_ * DK_];
__device__ float g_att[B_ * S_ * D_];

// ---------------------------------------------------------------------------
// SGEMM: out = A @ W^T + bias.  mode 0: plain [M,N] row-major.
// mode 1: scatter to [B,H,S,DK] head layout (row m=b*S+s, col n=h*DK+dk).
// ---------------------------------------------------------------------------
__global__ __launch_bounds__(256) void gemm_xwT(
    const float* __restrict__ A, const float* __restrict__ W,
    const float* __restrict__ bias, float* __restrict__ out, int mode)
{
    __shared__ float As[BK_][BM_];
    __shared__ float Bs[BK_][BN_];

    const int tid  = threadIdx.x;
    const int m0   = blockIdx.y * BM_;
    const int n0   = blockIdx.x * BN_;
    const int tRow = (tid >> 4) * TM_;
    const int tCol = (tid & 15) * TN_;
    const int lRow = tid >> 1;          // 0..127
    const int lCol = (tid & 1) * 4;     // 0 or 4

    float acc[TM_][TN_] = {};

    const float* Aptr = A + (size_t)(m0 + lRow) * GK + lCol;
    const float* Wptr = W + (size_t)(n0 + lRow) * GK + lCol;

    for (int k0 = 0; k0 < GK; k0 += BK_) {
        float4 av = *(const float4*)(Aptr + k0);
        float4 wv = *(const float4*)(Wptr + k0);
        As[lCol + 0][lRow] = av.x; As[lCol + 1][lRow] = av.y;
        As[lCol + 2][lRow] = av.z; As[lCol + 3][lRow] = av.w;
        Bs[lCol + 0][lRow] = wv.x; Bs[lCol + 1][lRow] = wv.y;
        Bs[lCol + 2][lRow] = wv.z; Bs[lCol + 3][lRow] = wv.w;
        __syncthreads();

#pragma unroll
        for (int k = 0; k < BK_; ++k) {
            float ra[TM_], rb[TN_];
#pragma unroll
            for (int i = 0; i < TM_; ++i) ra[i] = As[k][tRow + i];
#pragma unroll
            for (int j = 0; j < TN_; ++j) rb[j] = Bs[k][tCol + j];
#pragma unroll
            for (int i = 0; i < TM_; ++i)
#pragma unroll
                for (int j = 0; j < TN_; ++j)
                    acc[i][j] = fmaf(ra[i], rb[j], acc[i][j]);
        }
        __syncthreads();
    }

#pragma unroll
    for (int i = 0; i < TM_; ++i) {
        const int row = m0 + tRow + i;
#pragma unroll
        for (int j = 0; j < TN_; ++j) {
            const int col = n0 + tCol + j;
            const float v = acc[i][j] + bias[col];
            if (mode == 0) {
                out[(size_t)row * GN + col] = v;
            } else {
                const int b = row >> 10, s = row & (S_ - 1);
                const int h = col >> 6,  dk = col & (DK_ - 1);
                out[(((size_t)(b * H_ + h)) * S_ + s) * DK_ + dk] = v;
            }
        }
    }
}

// ---------------------------------------------------------------------------
// Fused flash attention with mask|diag and post-softmax group_prob reweight.
// Block: (q-tile of 64 rows) x (one b,h).  256 threads: ty=tid/16 owns 4 q
// rows, tx=tid%16 owns 4 k cols (scores) / 4 dk dims (output).
// out = sum_k exp(s-m)*g*V / sum_k exp(s-m)
// ---------------------------------------------------------------------------
__global__ __launch_bounds__(256) void attn_kernel(
    const float* __restrict__ Q, const float* __restrict__ K,
    const float* __restrict__ V, const int* __restrict__ mask,
    const float* __restrict__ gp, float* __restrict__ att)
{
    extern __shared__ float sm[];
    float* Qs  = sm;                 // [64][LDS]  Q tile
    float* KVs = sm + 64 * LDS;      // K^T tile [dk][kr], later V tile [kr][dk]
    float* Ps  = sm + 2 * 64 * LDS;  // weighted probs [q][k]

    const int tid = threadIdx.x;
    const int tx  = tid & 15;
    const int ty  = tid >> 4;
    const int bh  = blockIdx.y;
    const int b   = bh >> 4;
    const int h   = bh & 15;
    const int q0  = blockIdx.x * BQ;
    const float scale = 0.125f;  // 1/sqrt(64)

    const float* Qb = Q + (size_t)bh * S_ * DK_;
    const float* Kb = K + (size_t)bh * S_ * DK_;
    const float* Vb = V + (size_t)bh * S_ * DK_;

    // Load Q tile (coalesced): 64 rows x 64 cols
#pragma unroll
    for (int it = 0; it < 4; ++it) {
        const int row = ty + it * 16;
        const int c4  = tx * 4;
        float4 v = *(const float4*)&Qb[(size_t)(q0 + row) * DK_ + c4];
        *(float4*)&Qs[row * LDS + c4] = v;
    }

    float m_i[4], l_i[4], acc[4][4];
#pragma unroll
    for (int i = 0; i < 4; ++i) {
        m_i[i] = -1e30f;
        l_i[i] = 0.f;
#pragma unroll
        for (int j = 0; j < 4; ++j) acc[i][j] = 0.f;
    }

    for (int kt = 0; kt < S_; kt += BKT) {
        __syncthreads();  // prior-iter PV reads done; Q visible on first iter

        // Load K tile transposed: KVs[dk][kr]
#pragma unroll
        for (int it = 0; it < 4; ++it) {
            const int row = ty + it * 16;
            const int c4  = tx * 4;
            float4 v = *(const float4*)&Kb[(size_t)(kt + row) * DK_ + c4];
            KVs[(c4 + 0) * LDS + row] = v.x;
            KVs[(c4 + 1) * LDS + row] = v.y;
            KVs[(c4 + 2) * LDS + row] = v.z;
            KVs[(c4 + 3) * LDS + row] = v.w;
        }
        __syncthreads();

        // Scores s[i][j] = Q[r_i] . K[c_j]
        float s[4][4] = {};
#pragma unroll
        for (int d = 0; d < DK_; ++d) {
            float4 k4 = *(const float4*)&KVs[d * LDS + tx * 4];
#pragma unroll
            for (int i = 0; i < 4; ++i) {
                const float qv = Qs[(ty * 4 + i) * LDS + d];
                s[i][0] = fmaf(qv, k4.x, s[i][0]);
                s[i][1] = fmaf(qv, k4.y, s[i][1]);
                s[i][2] = fmaf(qv, k4.z, s[i][2]);
                s[i][3] = fmaf(qv, k4.w, s[i][3]);
            }
        }

        // Mask + online softmax (per q row, reduced across 16 tx lanes)
#pragma unroll
        for (int i = 0; i < 4; ++i) {
            const int qg = q0 + ty * 4 + i;
            const int4   mv4 = *(const int4*)&mask[((size_t)b * S_ + qg) * S_ + kt + tx * 4];
            const float4 gp4 = *(const float4*)&gp[((size_t)b * S_ + qg) * S_ + kt + tx * 4];

            float sv[4];
            const int kbase = kt + tx * 4;
            sv[0] = (mv4.x != 0 || qg == kbase + 0) ? s[i][0] * scale : -1e9f;
            sv[1] = (mv4.y != 0 || qg == kbase + 1) ? s[i][1] * scale : -1e9f;
            sv[2] = (mv4.z != 0 || qg == kbase + 2) ? s[i][2] * scale : -1e9f;
            sv[3] = (mv4.w != 0 || qg == kbase + 3) ? s[i][3] * scale : -1e9f;

            float mx = fmaxf(fmaxf(sv[0], sv[1]), fmaxf(sv[2], sv[3]));
#pragma unroll
            for (int off = 8; off >= 1; off >>= 1)
                mx = fmaxf(mx, __shfl_xor_sync(0xffffffffu, mx, off, 16));

            const float mnew = fmaxf(m_i[i], mx);
            const float corr = __expf(m_i[i] - mnew);

            float e[4], lsum = 0.f;
#pragma unroll
            for (int j = 0; j < 4; ++j) {
                e[j] = __expf(sv[j] - mnew);
                lsum += e[j];
            }
#pragma unroll
            for (int off = 8; off >= 1; off >>= 1)
                lsum += __shfl_xor_sync(0xffffffffu, lsum, off, 16);

            l_i[i] = l_i[i] * corr + lsum;
            m_i[i] = mnew;
#pragma unroll
            for (int j = 0; j < 4; ++j) acc[i][j] *= corr;

            float4 pv;
            pv.x = e[0] * gp4.x; pv.y = e[1] * gp4.y;
            pv.z = e[2] * gp4.z; pv.w = e[3] * gp4.w;
            *(float4*)&Ps[(ty * 4 + i) * LDS + tx * 4] = pv;
        }
        __syncthreads();  // Ps written; Kts reads done

        // Load V tile over KVs: [kr][dk]
#pragma unroll
        for (int it = 0; it < 4; ++it) {
            const int row = ty + it * 16;
            const int c4  = tx * 4;
            float4 v = *(const float4*)&Vb[(size_t)(kt + row) * DK_ + c4];
            *(float4*)&KVs[row * LDS + c4] = v;
        }
        __syncthreads();

        // PV: acc[i][:] += sum_k Ps[r_i][k] * V[k][dk(tx)]
#pragma unroll
        for (int k = 0; k < BKT; ++k) {
            float4 v4 = *(const float4*)&KVs[k * LDS + tx * 4];
#pragma unroll
            for (int i = 0; i < 4; ++i) {
                const float p = Ps[(ty * 4 + i) * LDS + k];
                acc[i][0] = fmaf(p, v4.x, acc[i][0]);
                acc[i][1] = fmaf(p, v4.y, acc[i][1]);
                acc[i][2] = fmaf(p, v4.z, acc[i][2]);
                acc[i][3] = fmaf(p, v4.w, acc[i][3]);
            }
        }
    }

    // Epilogue: divide by softmax denominator, write [B,S,D] layout
#pragma unroll
    for (int i = 0; i < 4; ++i) {
        const float inv = 1.0f / l_i[i];
        const int qg = q0 + ty * 4 + i;
        float4 o;
        o.x = acc[i][0] * inv; o.y = acc[i][1] * inv;
        o.z = acc[i][2] * inv; o.w = acc[i][3] * inv;
        *(float4*)&g_att[((size_t)b * S_ + qg) * D_ + h * DK_ + tx * 4] = o;
    }
}

// ---------------------------------------------------------------------------
extern "C" void kernel_launch(void* const* d_in, const int* in_sizes, int n_in,
                              void* d_out, int out_size)
{
    const float* query = (const float*)d_in[0];
    const float* key   = (const float*)d_in[1];
    const float* value = (const float*)d_in[2];
    const int*   mask  = (const int*)  d_in[3];
    const float* gprob = (const float*)d_in[4];
    const float* Wq = (const float*)d_in[5];
    const float* bq = (const float*)d_in[6];
    const float* Wk = (const float*)d_in[7];
    const float* bk = (const float*)d_in[8];
    const float* Wv = (const float*)d_in[9];
    const float* bv = (const float*)d_in[10];
    const float* Wo = (const float*)d_in[11];
    const float* bo = (const float*)d_in[12];
    float* out = (float*)d_out;

    float *qp, *kp, *vp, *ap;
    cudaGetSymbolAddress((void**)&qp, g_q);
    cudaGetSymbolAddress((void**)&kp, g_k);
    cudaGetSymbolAddress((void**)&vp, g_v);
    cudaGetSymbolAddress((void**)&ap, g_att);

    cudaFuncSetAttribute(attn_kernel,
                         cudaFuncAttributeMaxDynamicSharedMemorySize, ATTN_SMEM);

    dim3 gg(GN / BN_, GM / BM_);
    gemm_xwT<<<gg, 256>>>(query, Wq, bq, qp, 1);
    gemm_xwT<<<gg, 256>>>(key,   Wk, bk, kp, 1);
    gemm_xwT<<<gg, 256>>>(value, Wv, bv, vp, 1);

    attn_kernel<<<dim3(S_ / BQ, B_ * H_), 256, ATTN_SMEM>>>(
        qp, kp, vp, mask, gprob, ap);

    gemm_xwT<<<gg, 256>>>(ap, Wo, bo, out, 0);
}

// round 3
// speedup vs baseline: 1.5110x; 1.5110x over previous
#include <cuda_runtime.h>
#include <math.h>
#include <stdint.h>

// Problem constants
#define B_   4
#define S_   1024
#define D_   1024
#define H_   16
#define DK_  64

#define GM   4096
#define GN   1024
#define GK   1024

// tf32 GEMM tiling
#define BM_  128
#define BN_  128
#define BK_  32
#define PAD  36                      // smem row stride (floats)
#define TILE_F (BM_ * PAD)           // floats per smem plane
#define GEMM_SMEM (4 * TILE_F * 4)   // Ah, Al, Wh, Wl

// Attention tiling
#define BQ   64
#define BKT  64
#define LDS  68
#define ATTN_SMEM (3 * 64 * LDS * 4)

// Scratch (allocation-free rule: __device__ globals)
__device__ float g_q[B_ * H_ * S_ * DK_];
__device__ float g_k[B_ * H_ * S_ * DK_];
__device__ float g_v[B_ * H_ * S_ * DK_];
__device__ float g_att[B_ * S_ * D_];

// ---------------------------------------------------------------------------
// tf32 helpers
// ---------------------------------------------------------------------------
__device__ __forceinline__ uint32_t f2tf(float x) {
    uint32_t u;
    asm("cvt.rna.tf32.f32 %0, %1;" : "=r"(u) : "f"(x));
    return u;
}

__device__ __forceinline__ void mma_tf32(
    float c[4], uint32_t a0, uint32_t a1, uint32_t a2, uint32_t a3,
    uint32_t b0, uint32_t b1)
{
    asm volatile(
        "mma.sync.aligned.m16n8k8.row.col.f32.tf32.tf32.f32 "
        "{%0,%1,%2,%3}, {%4,%5,%6,%7}, {%8,%9}, {%0,%1,%2,%3};\n"
        : "+f"(c[0]), "+f"(c[1]), "+f"(c[2]), "+f"(c[3])
        : "r"(a0), "r"(a1), "r"(a2), "r"(a3), "r"(b0), "r"(b1));
}

// split x into tf32 hi + tf32 lo (stored as floats carrying tf32 bit patterns)
__device__ __forceinline__ void split_store(
    float* __restrict__ hiP, float* __restrict__ loP, int idx, float4 v)
{
    float h0 = __uint_as_float(f2tf(v.x));
    float h1 = __uint_as_float(f2tf(v.y));
    float h2 = __uint_as_float(f2tf(v.z));
    float h3 = __uint_as_float(f2tf(v.w));
    float4 hv = {h0, h1, h2, h3};
    float4 lv = {__uint_as_float(f2tf(v.x - h0)),
                 __uint_as_float(f2tf(v.y - h1)),
                 __uint_as_float(f2tf(v.z - h2)),
                 __uint_as_float(f2tf(v.w - h3))};
    *(float4*)&hiP[idx] = hv;
    *(float4*)&loP[idx] = lv;
}

// ---------------------------------------------------------------------------
// tf32x3 GEMM body: out = A @ W^T + bias.
// mode 0: [M,N] row-major. mode 1: scatter to [B,H,S,DK].
// ---------------------------------------------------------------------------
__device__ __forceinline__ void gemm_tf32_body(
    const float* __restrict__ A, const float* __restrict__ W,
    const float* __restrict__ bias, float* __restrict__ out, int mode)
{
    extern __shared__ float smemF[];
    float* Ah = smemF;
    float* Al = smemF + TILE_F;
    float* Wh = smemF + 2 * TILE_F;
    float* Wl = smemF + 3 * TILE_F;

    const int tid  = threadIdx.x;
    const int lane = tid & 31;
    const int warp = tid >> 5;
    const int wm   = warp & 1;          // 2 m-warps
    const int wn   = warp >> 1;         // 4 n-warps
    const int g    = lane >> 2;         // 0..7
    const int t    = lane & 3;          // 0..3

    const int m0 = blockIdx.y * BM_;
    const int n0 = blockIdx.x * BN_;

    // staging: thread loads rows r of A and W, 16 cols starting at cHalf
    const int r     = tid >> 1;
    const int cHalf = (tid & 1) * 16;

    const float* Aptr = A + (size_t)(m0 + r) * GK + cHalf;
    const float* Wptr = W + (size_t)(n0 + r) * GK + cHalf;

    float c[4][4][4];
#pragma unroll
    for (int i = 0; i < 4; ++i)
#pragma unroll
        for (int j = 0; j < 4; ++j)
#pragma unroll
            for (int e = 0; e < 4; ++e) c[i][j][e] = 0.f;

    float4 aR[4], wR[4];
#pragma unroll
    for (int i = 0; i < 4; ++i) {
        aR[i] = *(const float4*)(Aptr + 4 * i);
        wR[i] = *(const float4*)(Wptr + 4 * i);
    }

    for (int k0 = 0; k0 < GK; k0 += BK_) {
        __syncthreads();
        // convert + store current tile
#pragma unroll
        for (int i = 0; i < 4; ++i) {
            const int idx = r * PAD + cHalf + 4 * i;
            split_store(Ah, Al, idx, aR[i]);
            split_store(Wh, Wl, idx, wR[i]);
        }
        __syncthreads();

        // prefetch next tile into regs (hidden under mma)
        if (k0 + BK_ < GK) {
#pragma unroll
            for (int i = 0; i < 4; ++i) {
                aR[i] = *(const float4*)(Aptr + k0 + BK_ + 4 * i);
                wR[i] = *(const float4*)(Wptr + k0 + BK_ + 4 * i);
            }
        }

#pragma unroll
        for (int kk = 0; kk < BK_; kk += 8) {
            uint32_t ahi[4][4], alo[4][4], bhi[4][2], blo[4][2];
#pragma unroll
            for (int mi = 0; mi < 4; ++mi) {
                const int r0 = (wm * 64 + mi * 16 + g) * PAD + kk + t;
                const int r1 = r0 + 8 * PAD;
                ahi[mi][0] = __float_as_uint(Ah[r0]);
                ahi[mi][1] = __float_as_uint(Ah[r1]);
                ahi[mi][2] = __float_as_uint(Ah[r0 + 4]);
                ahi[mi][3] = __float_as_uint(Ah[r1 + 4]);
                alo[mi][0] = __float_as_uint(Al[r0]);
                alo[mi][1] = __float_as_uint(Al[r1]);
                alo[mi][2] = __float_as_uint(Al[r0 + 4]);
                alo[mi][3] = __float_as_uint(Al[r1 + 4]);
            }
#pragma unroll
            for (int ni = 0; ni < 4; ++ni) {
                const int c0 = (wn * 32 + ni * 8 + g) * PAD + kk + t;
                bhi[ni][0] = __float_as_uint(Wh[c0]);
                bhi[ni][1] = __float_as_uint(Wh[c0 + 4]);
                blo[ni][0] = __float_as_uint(Wl[c0]);
                blo[ni][1] = __float_as_uint(Wl[c0 + 4]);
            }
#pragma unroll
            for (int mi = 0; mi < 4; ++mi)
#pragma unroll
                for (int ni = 0; ni < 4; ++ni) {
                    mma_tf32(c[mi][ni], ahi[mi][0], ahi[mi][1], ahi[mi][2], ahi[mi][3],
                             bhi[ni][0], bhi[ni][1]);
                    mma_tf32(c[mi][ni], ahi[mi][0], ahi[mi][1], ahi[mi][2], ahi[mi][3],
                             blo[ni][0], blo[ni][1]);
                    mma_tf32(c[mi][ni], alo[mi][0], alo[mi][1], alo[mi][2], alo[mi][3],
                             bhi[ni][0], bhi[ni][1]);
                }
        }
    }

    // epilogue
#pragma unroll
    for (int mi = 0; mi < 4; ++mi) {
        const int row0 = m0 + wm * 64 + mi * 16 + g;
        const int row1 = row0 + 8;
#pragma unroll
        for (int ni = 0; ni < 4; ++ni) {
            const int col = n0 + wn * 32 + ni * 8 + t * 2;
            const float b0v = bias[col], b1v = bias[col + 1];
            float2 o0 = {c[mi][ni][0] + b0v, c[mi][ni][1] + b1v};
            float2 o1 = {c[mi][ni][2] + b0v, c[mi][ni][3] + b1v};
            if (mode == 0) {
                *(float2*)&out[(size_t)row0 * GN + col] = o0;
                *(float2*)&out[(size_t)row1 * GN + col] = o1;
            } else {
                const int h  = col >> 6, dk = col & (DK_ - 1);
                const int b0r = row0 >> 10, s0 = row0 & (S_ - 1);
                const int b1r = row1 >> 10, s1 = row1 & (S_ - 1);
                *(float2*)&out[(((size_t)(b0r * H_ + h)) * S_ + s0) * DK_ + dk] = o0;
                *(float2*)&out[(((size_t)(b1r * H_ + h)) * S_ + s1) * DK_ + dk] = o1;
            }
        }
    }
}

__global__ __launch_bounds__(256) void qkv_gemm(
    const float* __restrict__ x0, const float* __restrict__ x1, const float* __restrict__ x2,
    const float* __restrict__ W0, const float* __restrict__ W1, const float* __restrict__ W2,
    const float* __restrict__ b0, const float* __restrict__ b1, const float* __restrict__ b2,
    float* o0, float* o1, float* o2)
{
    const float* A; const float* W; const float* bi; float* o;
    if (blockIdx.z == 0)      { A = x0; W = W0; bi = b0; o = o0; }
    else if (blockIdx.z == 1) { A = x1; W = W1; bi = b1; o = o1; }
    else                      { A = x2; W = W2; bi = b2; o = o2; }
    gemm_tf32_body(A, W, bi, o, 1);
}

__global__ __launch_bounds__(256) void out_gemm(
    const float* __restrict__ A, const float* __restrict__ W,
    const float* __restrict__ bias, float* __restrict__ out)
{
    gemm_tf32_body(A, W, bias, out, 0);
}

// ---------------------------------------------------------------------------
// Fused flash attention (unchanged from Round 1)
// ---------------------------------------------------------------------------
__global__ __launch_bounds__(256) void attn_kernel(
    const float* __restrict__ Q, const float* __restrict__ K,
    const float* __restrict__ V, const int* __restrict__ mask,
    const float* __restrict__ gp, float* __restrict__ att)
{
    extern __shared__ float sm[];
    float* Qs  = sm;
    float* KVs = sm + 64 * LDS;
    float* Ps  = sm + 2 * 64 * LDS;

    const int tid = threadIdx.x;
    const int tx  = tid & 15;
    const int ty  = tid >> 4;
    const int bh  = blockIdx.y;
    const int b   = bh >> 4;
    const int h   = bh & 15;
    const int q0  = blockIdx.x * BQ;
    const float scale = 0.125f;

    const float* Qb = Q + (size_t)bh * S_ * DK_;
    const float* Kb = K + (size_t)bh * S_ * DK_;
    const float* Vb = V + (size_t)bh * S_ * DK_;

#pragma unroll
    for (int it = 0; it < 4; ++it) {
        const int row = ty + it * 16;
        const int c4  = tx * 4;
        float4 v = *(const float4*)&Qb[(size_t)(q0 + row) * DK_ + c4];
        *(float4*)&Qs[row * LDS + c4] = v;
    }

    float m_i[4], l_i[4], acc[4][4];
#pragma unroll
    for (int i = 0; i < 4; ++i) {
        m_i[i] = -1e30f;
        l_i[i] = 0.f;
#pragma unroll
        for (int j = 0; j < 4; ++j) acc[i][j] = 0.f;
    }

    for (int kt = 0; kt < S_; kt += BKT) {
        __syncthreads();

#pragma unroll
        for (int it = 0; it < 4; ++it) {
            const int row = ty + it * 16;
            const int c4  = tx * 4;
            float4 v = *(const float4*)&Kb[(size_t)(kt + row) * DK_ + c4];
            KVs[(c4 + 0) * LDS + row] = v.x;
            KVs[(c4 + 1) * LDS + row] = v.y;
            KVs[(c4 + 2) * LDS + row] = v.z;
            KVs[(c4 + 3) * LDS + row] = v.w;
        }
        __syncthreads();

        float s[4][4] = {};
#pragma unroll
        for (int d = 0; d < DK_; ++d) {
            float4 k4 = *(const float4*)&KVs[d * LDS + tx * 4];
#pragma unroll
            for (int i = 0; i < 4; ++i) {
                const float qv = Qs[(ty * 4 + i) * LDS + d];
                s[i][0] = fmaf(qv, k4.x, s[i][0]);
                s[i][1] = fmaf(qv, k4.y, s[i][1]);
                s[i][2] = fmaf(qv, k4.z, s[i][2]);
                s[i][3] = fmaf(qv, k4.w, s[i][3]);
            }
        }

#pragma unroll
        for (int i = 0; i < 4; ++i) {
            const int qg = q0 + ty * 4 + i;
            const int4   mv4 = *(const int4*)&mask[((size_t)b * S_ + qg) * S_ + kt + tx * 4];
            const float4 gp4 = *(const float4*)&gp[((size_t)b * S_ + qg) * S_ + kt + tx * 4];

            float sv[4];
            const int kbase = kt + tx * 4;
            sv[0] = (mv4.x != 0 || qg == kbase + 0) ? s[i][0] * scale : -1e9f;
            sv[1] = (mv4.y != 0 || qg == kbase + 1) ? s[i][1] * scale : -1e9f;
            sv[2] = (mv4.z != 0 || qg == kbase + 2) ? s[i][2] * scale : -1e9f;
            sv[3] = (mv4.w != 0 || qg == kbase + 3) ? s[i][3] * scale : -1e9f;

            float mx = fmaxf(fmaxf(sv[0], sv[1]), fmaxf(sv[2], sv[3]));
#pragma unroll
            for (int off = 8; off >= 1; off >>= 1)
                mx = fmaxf(mx, __shfl_xor_sync(0xffffffffu, mx, off, 16));

            const float mnew = fmaxf(m_i[i], mx);
            const float corr = __expf(m_i[i] - mnew);

            float e[4], lsum = 0.f;
#pragma unroll
            for (int j = 0; j < 4; ++j) {
                e[j] = __expf(sv[j] - mnew);
                lsum += e[j];
            }
#pragma unroll
            for (int off = 8; off >= 1; off >>= 1)
                lsum += __shfl_xor_sync(0xffffffffu, lsum, off, 16);

            l_i[i] = l_i[i] * corr + lsum;
            m_i[i] = mnew;
#pragma unroll
            for (int j = 0; j < 4; ++j) acc[i][j] *= corr;

            float4 pv;
            pv.x = e[0] * gp4.x; pv.y = e[1] * gp4.y;
            pv.z = e[2] * gp4.z; pv.w = e[3] * gp4.w;
            *(float4*)&Ps[(ty * 4 + i) * LDS + tx * 4] = pv;
        }
        __syncthreads();

#pragma unroll
        for (int it = 0; it < 4; ++it) {
            const int row = ty + it * 16;
            const int c4  = tx * 4;
            float4 v = *(const float4*)&Vb[(size_t)(kt + row) * DK_ + c4];
            *(float4*)&KVs[row * LDS + c4] = v;
        }
        __syncthreads();

#pragma unroll
        for (int k = 0; k < BKT; ++k) {
            float4 v4 = *(const float4*)&KVs[k * LDS + tx * 4];
#pragma unroll
            for (int i = 0; i < 4; ++i) {
                const float p = Ps[(ty * 4 + i) * LDS + k];
                acc[i][0] = fmaf(p, v4.x, acc[i][0]);
                acc[i][1] = fmaf(p, v4.y, acc[i][1]);
                acc[i][2] = fmaf(p, v4.z, acc[i][2]);
                acc[i][3] = fmaf(p, v4.w, acc[i][3]);
            }
        }
    }

#pragma unroll
    for (int i = 0; i < 4; ++i) {
        const float inv = 1.0f / l_i[i];
        const int qg = q0 + ty * 4 + i;
        float4 o;
        o.x = acc[i][0] * inv; o.y = acc[i][1] * inv;
        o.z = acc[i][2] * inv; o.w = acc[i][3] * inv;
        *(float4*)&g_att[((size_t)b * S_ + qg) * D_ + h * DK_ + tx * 4] = o;
    }
}

// ---------------------------------------------------------------------------
extern "C" void kernel_launch(void* const* d_in, const int* in_sizes, int n_in,
                              void* d_out, int out_size)
{
    const float* query = (const float*)d_in[0];
    const float* key   = (const float*)d_in[1];
    const float* value = (const float*)d_in[2];
    const int*   mask  = (const int*)  d_in[3];
    const float* gprob = (const float*)d_in[4];
    const float* Wq = (const float*)d_in[5];
    const float* bq = (const float*)d_in[6];
    const float* Wk = (const float*)d_in[7];
    const float* bk = (const float*)d_in[8];
    const float* Wv = (const float*)d_in[9];
    const float* bv = (const float*)d_in[10];
    const float* Wo = (const float*)d_in[11];
    const float* bo = (const float*)d_in[12];
    float* out = (float*)d_out;

    float *qp, *kp, *vp, *ap;
    cudaGetSymbolAddress((void**)&qp, g_q);
    cudaGetSymbolAddress((void**)&kp, g_k);
    cudaGetSymbolAddress((void**)&vp, g_v);
    cudaGetSymbolAddress((void**)&ap, g_att);

    cudaFuncSetAttribute(attn_kernel,
                         cudaFuncAttributeMaxDynamicSharedMemorySize, ATTN_SMEM);
    cudaFuncSetAttribute(qkv_gemm,
                         cudaFuncAttributeMaxDynamicSharedMemorySize, GEMM_SMEM);
    cudaFuncSetAttribute(out_gemm,
                         cudaFuncAttributeMaxDynamicSharedMemorySize, GEMM_SMEM);

    dim3 gqkv(GN / BN_, GM / BM_, 3);
    qkv_gemm<<<gqkv, 256, GEMM_SMEM>>>(query, key, value,
                                       Wq, Wk, Wv, bq, bk, bv,
                                       qp, kp, vp);

    attn_kernel<<<dim3(S_ / BQ, B_ * H_), 256, ATTN_SMEM>>>(
        qp, kp, vp, mask, gprob, ap);

    out_gemm<<<dim3(GN / BN_, GM / BM_), 256, GEMM_SMEM>>>(ap, Wo, bo, out);
}

// round 4
// speedup vs baseline: 1.7706x; 1.1718x over previous
#include <cuda_runtime.h>
#include <cuda_bf16.h>
#include <math.h>
#include <stdint.h>

// Problem constants
#define B_   4
#define S_   1024
#define D_   1024
#define H_   16
#define DK_  64

#define GM   4096
#define GN   1024
#define GK   1024

// bf16x3 GEMM tiling
#define BM_  128
#define BN_  128
#define BK_  32                       // k-extent of one smem tile (elements)
#define SB   40                       // smem row stride in bf16 (80B = 20 banks: conflict-free)
#define PF   (BM_ * SB)               // bf16 elements per plane
#define GEMM_SMEM (2 * 4 * PF * 2)    // 2 buffers x (Ah,Al,Wh,Wl) x bf16

// Attention tiling
#define BQ   64
#define BKT  64
#define LDS  68
#define ATTN_SMEM (3 * 64 * LDS * 4)

// Scratch (allocation-free rule: __device__ globals)
__device__ float g_q[B_ * H_ * S_ * DK_];
__device__ float g_k[B_ * H_ * S_ * DK_];
__device__ float g_v[B_ * H_ * S_ * DK_];
__device__ float g_att[B_ * S_ * D_];

// ---------------------------------------------------------------------------
// bf16 helpers
// ---------------------------------------------------------------------------
__device__ __forceinline__ uint32_t packbf2(float lo_e, float hi_e) {
    // low 16 bits = bf16(lo_e), high 16 bits = bf16(hi_e)
    uint32_t r;
    asm("cvt.rn.bf16x2.f32 %0, %1, %2;" : "=r"(r) : "f"(hi_e), "f"(lo_e));
    return r;
}

// split two floats into packed bf16x2 hi + bf16x2 lo
__device__ __forceinline__ void split2(float x0, float x1,
                                       uint32_t& hp, uint32_t& lp) {
    hp = packbf2(x0, x1);
    float h0 = __uint_as_float(hp << 16);
    float h1 = __uint_as_float(hp & 0xffff0000u);
    lp = packbf2(x0 - h0, x1 - h1);
}

// convert 16 floats (4x float4) -> 16 bf16 hi + 16 bf16 lo, store to smem
__device__ __forceinline__ void split_store16(
    __nv_bfloat16* __restrict__ hiP, __nv_bfloat16* __restrict__ loP,
    int idx, const float4* v)
{
    uint32_t h[8], l[8];
#pragma unroll
    for (int i = 0; i < 4; ++i) {
        split2(v[i].x, v[i].y, h[2 * i], l[2 * i]);
        split2(v[i].z, v[i].w, h[2 * i + 1], l[2 * i + 1]);
    }
    *(uint4*)&hiP[idx]     = make_uint4(h[0], h[1], h[2], h[3]);
    *(uint4*)&hiP[idx + 8] = make_uint4(h[4], h[5], h[6], h[7]);
    *(uint4*)&loP[idx]     = make_uint4(l[0], l[1], l[2], l[3]);
    *(uint4*)&loP[idx + 8] = make_uint4(l[4], l[5], l[6], l[7]);
}

__device__ __forceinline__ void mma_bf16(
    float c[4], uint32_t a0, uint32_t a1, uint32_t a2, uint32_t a3,
    uint32_t b0, uint32_t b1)
{
    asm volatile(
        "mma.sync.aligned.m16n8k16.row.col.f32.bf16.bf16.f32 "
        "{%0,%1,%2,%3}, {%4,%5,%6,%7}, {%8,%9}, {%0,%1,%2,%3};\n"
        : "+f"(c[0]), "+f"(c[1]), "+f"(c[2]), "+f"(c[3])
        : "r"(a0), "r"(a1), "r"(a2), "r"(a3), "r"(b0), "r"(b1));
}

// ---------------------------------------------------------------------------
// bf16x3 GEMM body: out = A @ W^T + bias.
// mode 0: [M,N] row-major. mode 1: scatter to [B,H,S,DK].
// Double-buffered smem, one __syncthreads per k-tile.
// ---------------------------------------------------------------------------
__device__ __forceinline__ void gemm_bf16_body(
    const float* __restrict__ A, const float* __restrict__ W,
    const float* __restrict__ bias, float* __restrict__ out, int mode)
{
    extern __shared__ __align__(16) char smemRaw[];
    __nv_bfloat16* base = (__nv_bfloat16*)smemRaw;

    const int tid  = threadIdx.x;
    const int lane = tid & 31;
    const int warp = tid >> 5;
    const int wm   = warp & 1;          // 2 m-warps
    const int wn   = warp >> 1;         // 4 n-warps
    const int g    = lane >> 2;         // 0..7
    const int t    = lane & 3;          // 0..3

    const int m0 = blockIdx.y * BM_;
    const int n0 = blockIdx.x * BN_;

    // staging: thread loads row r, 16 cols starting at cHalf
    const int r     = tid >> 1;
    const int cHalf = (tid & 1) * 16;

    const float* Aptr = A + (size_t)(m0 + r) * GK + cHalf;
    const float* Wptr = W + (size_t)(n0 + r) * GK + cHalf;

    float c[4][4][4];
#pragma unroll
    for (int i = 0; i < 4; ++i)
#pragma unroll
        for (int j = 0; j < 4; ++j)
#pragma unroll
            for (int e = 0; e < 4; ++e) c[i][j][e] = 0.f;

    const int KT = GK / BK_;            // 32 tiles
    const int stIdx = r * SB + cHalf;   // bf16 element index for STS

    float4 aR[4], wR[4];

    // regs <- tile 0
#pragma unroll
    for (int i = 0; i < 4; ++i) {
        aR[i] = *(const float4*)(Aptr + 4 * i);
        wR[i] = *(const float4*)(Wptr + 4 * i);
    }
    // buf0 <- tile 0
    split_store16(base + 0 * PF, base + 1 * PF, stIdx, aR);
    split_store16(base + 2 * PF, base + 3 * PF, stIdx, wR);
    // regs <- tile 1
#pragma unroll
    for (int i = 0; i < 4; ++i) {
        aR[i] = *(const float4*)(Aptr + BK_ + 4 * i);
        wR[i] = *(const float4*)(Wptr + BK_ + 4 * i);
    }
    __syncthreads();

    int p = 0;
    for (int tt = 0; tt < KT; ++tt) {
        // stage tile tt+1 into other buffer (overlaps mma below)
        if (tt + 1 < KT) {
            __nv_bfloat16* nb = base + (p ^ 1) * 4 * PF;
            split_store16(nb + 0 * PF, nb + 1 * PF, stIdx, aR);
            split_store16(nb + 2 * PF, nb + 3 * PF, stIdx, wR);
            if (tt + 2 < KT) {
                const int off = (tt + 2) * BK_;
#pragma unroll
                for (int i = 0; i < 4; ++i) {
                    aR[i] = *(const float4*)(Aptr + off + 4 * i);
                    wR[i] = *(const float4*)(Wptr + off + 4 * i);
                }
            }
        }

        const __nv_bfloat16* Ah = base + p * 4 * PF;
        const __nv_bfloat16* Al = Ah + PF;
        const __nv_bfloat16* Wh = Ah + 2 * PF;
        const __nv_bfloat16* Wl = Ah + 3 * PF;

#pragma unroll
        for (int kk = 0; kk < BK_; kk += 16) {
            uint32_t ahi[4][4], alo[4][4], bhi[4][2], blo[4][2];
#pragma unroll
            for (int mi = 0; mi < 4; ++mi) {
                const int ar = wm * 64 + mi * 16 + g;
                const int i00 = ar * SB + kk + t * 2;
                const int i10 = (ar + 8) * SB + kk + t * 2;
                ahi[mi][0] = *(const uint32_t*)&Ah[i00];
                ahi[mi][1] = *(const uint32_t*)&Ah[i10];
                ahi[mi][2] = *(const uint32_t*)&Ah[i00 + 8];
                ahi[mi][3] = *(const uint32_t*)&Ah[i10 + 8];
                alo[mi][0] = *(const uint32_t*)&Al[i00];
                alo[mi][1] = *(const uint32_t*)&Al[i10];
                alo[mi][2] = *(const uint32_t*)&Al[i00 + 8];
                alo[mi][3] = *(const uint32_t*)&Al[i10 + 8];
            }
#pragma unroll
            for (int ni = 0; ni < 4; ++ni) {
                const int br = wn * 32 + ni * 8 + g;
                const int i0 = br * SB + kk + t * 2;
                bhi[ni][0] = *(const uint32_t*)&Wh[i0];
                bhi[ni][1] = *(const uint32_t*)&Wh[i0 + 8];
                blo[ni][0] = *(const uint32_t*)&Wl[i0];
                blo[ni][1] = *(const uint32_t*)&Wl[i0 + 8];
            }
#pragma unroll
            for (int mi = 0; mi < 4; ++mi)
#pragma unroll
                for (int ni = 0; ni < 4; ++ni) {
                    mma_bf16(c[mi][ni], ahi[mi][0], ahi[mi][1], ahi[mi][2], ahi[mi][3],
                             bhi[ni][0], bhi[ni][1]);
                    mma_bf16(c[mi][ni], ahi[mi][0], ahi[mi][1], ahi[mi][2], ahi[mi][3],
                             blo[ni][0], blo[ni][1]);
                    mma_bf16(c[mi][ni], alo[mi][0], alo[mi][1], alo[mi][2], alo[mi][3],
                             bhi[ni][0], bhi[ni][1]);
                }
        }
        __syncthreads();
        p ^= 1;
    }

    // epilogue
#pragma unroll
    for (int mi = 0; mi < 4; ++mi) {
        const int row0 = m0 + wm * 64 + mi * 16 + g;
        const int row1 = row0 + 8;
#pragma unroll
        for (int ni = 0; ni < 4; ++ni) {
            const int col = n0 + wn * 32 + ni * 8 + t * 2;
            const float b0v = bias[col], b1v = bias[col + 1];
            float2 o0 = {c[mi][ni][0] + b0v, c[mi][ni][1] + b1v};
            float2 o1 = {c[mi][ni][2] + b0v, c[mi][ni][3] + b1v};
            if (mode == 0) {
                *(float2*)&out[(size_t)row0 * GN + col] = o0;
                *(float2*)&out[(size_t)row1 * GN + col] = o1;
            } else {
                const int h  = col >> 6, dk = col & (DK_ - 1);
                const int b0r = row0 >> 10, s0 = row0 & (S_ - 1);
                const int b1r = row1 >> 10, s1 = row1 & (S_ - 1);
                *(float2*)&out[(((size_t)(b0r * H_ + h)) * S_ + s0) * DK_ + dk] = o0;
                *(float2*)&out[(((size_t)(b1r * H_ + h)) * S_ + s1) * DK_ + dk] = o1;
            }
        }
    }
}

__global__ __launch_bounds__(256) void qkv_gemm(
    const float* __restrict__ x0, const float* __restrict__ x1, const float* __restrict__ x2,
    const float* __restrict__ W0, const float* __restrict__ W1, const float* __restrict__ W2,
    const float* __restrict__ b0, const float* __restrict__ b1, const float* __restrict__ b2,
    float* o0, float* o1, float* o2)
{
    const float* A; const float* W; const float* bi; float* o;
    if (blockIdx.z == 0)      { A = x0; W = W0; bi = b0; o = o0; }
    else if (blockIdx.z == 1) { A = x1; W = W1; bi = b1; o = o1; }
    else                      { A = x2; W = W2; bi = b2; o = o2; }
    gemm_bf16_body(A, W, bi, o, 1);
}

__global__ __launch_bounds__(256) void out_gemm(
    const float* __restrict__ A, const float* __restrict__ W,
    const float* __restrict__ bias, float* __restrict__ out)
{
    gemm_bf16_body(A, W, bias, out, 0);
}

// ---------------------------------------------------------------------------
// Fused flash attention (unchanged)
// ---------------------------------------------------------------------------
__global__ __launch_bounds__(256) void attn_kernel(
    const float* __restrict__ Q, const float* __restrict__ K,
    const float* __restrict__ V, const int* __restrict__ mask,
    const float* __restrict__ gp, float* __restrict__ att)
{
    extern __shared__ float sm[];
    float* Qs  = sm;
    float* KVs = sm + 64 * LDS;
    float* Ps  = sm + 2 * 64 * LDS;

    const int tid = threadIdx.x;
    const int tx  = tid & 15;
    const int ty  = tid >> 4;
    const int bh  = blockIdx.y;
    const int b   = bh >> 4;
    const int h   = bh & 15;
    const int q0  = blockIdx.x * BQ;
    const float scale = 0.125f;

    const float* Qb = Q + (size_t)bh * S_ * DK_;
    const float* Kb = K + (size_t)bh * S_ * DK_;
    const float* Vb = V + (size_t)bh * S_ * DK_;

#pragma unroll
    for (int it = 0; it < 4; ++it) {
        const int row = ty + it * 16;
        const int c4  = tx * 4;
        float4 v = *(const float4*)&Qb[(size_t)(q0 + row) * DK_ + c4];
        *(float4*)&Qs[row * LDS + c4] = v;
    }

    float m_i[4], l_i[4], acc[4][4];
#pragma unroll
    for (int i = 0; i < 4; ++i) {
        m_i[i] = -1e30f;
        l_i[i] = 0.f;
#pragma unroll
        for (int j = 0; j < 4; ++j) acc[i][j] = 0.f;
    }

    for (int kt = 0; kt < S_; kt += BKT) {
        __syncthreads();

#pragma unroll
        for (int it = 0; it < 4; ++it) {
            const int row = ty + it * 16;
            const int c4  = tx * 4;
            float4 v = *(const float4*)&Kb[(size_t)(kt + row) * DK_ + c4];
            KVs[(c4 + 0) * LDS + row] = v.x;
            KVs[(c4 + 1) * LDS + row] = v.y;
            KVs[(c4 + 2) * LDS + row] = v.z;
            KVs[(c4 + 3) * LDS + row] = v.w;
        }
        __syncthreads();

        float s[4][4] = {};
#pragma unroll
        for (int d = 0; d < DK_; ++d) {
            float4 k4 = *(const float4*)&KVs[d * LDS + tx * 4];
#pragma unroll
            for (int i = 0; i < 4; ++i) {
                const float qv = Qs[(ty * 4 + i) * LDS + d];
                s[i][0] = fmaf(qv, k4.x, s[i][0]);
                s[i][1] = fmaf(qv, k4.y, s[i][1]);
                s[i][2] = fmaf(qv, k4.z, s[i][2]);
                s[i][3] = fmaf(qv, k4.w, s[i][3]);
            }
        }

#pragma unroll
        for (int i = 0; i < 4; ++i) {
            const int qg = q0 + ty * 4 + i;
            const int4   mv4 = *(const int4*)&mask[((size_t)b * S_ + qg) * S_ + kt + tx * 4];
            const float4 gp4 = *(const float4*)&gp[((size_t)b * S_ + qg) * S_ + kt + tx * 4];

            float sv[4];
            const int kbase = kt + tx * 4;
            sv[0] = (mv4.x != 0 || qg == kbase + 0) ? s[i][0] * scale : -1e9f;
            sv[1] = (mv4.y != 0 || qg == kbase + 1) ? s[i][1] * scale : -1e9f;
            sv[2] = (mv4.z != 0 || qg == kbase + 2) ? s[i][2] * scale : -1e9f;
            sv[3] = (mv4.w != 0 || qg == kbase + 3) ? s[i][3] * scale : -1e9f;

            float mx = fmaxf(fmaxf(sv[0], sv[1]), fmaxf(sv[2], sv[3]));
#pragma unroll
            for (int off = 8; off >= 1; off >>= 1)
                mx = fmaxf(mx, __shfl_xor_sync(0xffffffffu, mx, off, 16));

            const float mnew = fmaxf(m_i[i], mx);
            const float corr = __expf(m_i[i] - mnew);

            float e[4], lsum = 0.f;
#pragma unroll
            for (int j = 0; j < 4; ++j) {
                e[j] = __expf(sv[j] - mnew);
                lsum += e[j];
            }
#pragma unroll
            for (int off = 8; off >= 1; off >>= 1)
                lsum += __shfl_xor_sync(0xffffffffu, lsum, off, 16);

            l_i[i] = l_i[i] * corr + lsum;
            m_i[i] = mnew;
#pragma unroll
            for (int j = 0; j < 4; ++j) acc[i][j] *= corr;

            float4 pv;
            pv.x = e[0] * gp4.x; pv.y = e[1] * gp4.y;
            pv.z = e[2] * gp4.z; pv.w = e[3] * gp4.w;
            *(float4*)&Ps[(ty * 4 + i) * LDS + tx * 4] = pv;
        }
        __syncthreads();

#pragma unroll
        for (int it = 0; it < 4; ++it) {
            const int row = ty + it * 16;
            const int c4  = tx * 4;
            float4 v = *(const float4*)&Vb[(size_t)(kt + row) * DK_ + c4];
            *(float4*)&KVs[row * LDS + c4] = v;
        }
        __syncthreads();

#pragma unroll
        for (int k = 0; k < BKT; ++k) {
            float4 v4 = *(const float4*)&KVs[k * LDS + tx * 4];
#pragma unroll
            for (int i = 0; i < 4; ++i) {
                const float p = Ps[(ty * 4 + i) * LDS + k];
                acc[i][0] = fmaf(p, v4.x, acc[i][0]);
                acc[i][1] = fmaf(p, v4.y, acc[i][1]);
                acc[i][2] = fmaf(p, v4.z, acc[i][2]);
                acc[i][3] = fmaf(p, v4.w, acc[i][3]);
            }
        }
    }

#pragma unroll
    for (int i = 0; i < 4; ++i) {
        const float inv = 1.0f / l_i[i];
        const int qg = q0 + ty * 4 + i;
        float4 o;
        o.x = acc[i][0] * inv; o.y = acc[i][1] * inv;
        o.z = acc[i][2] * inv; o.w = acc[i][3] * inv;
        *(float4*)&g_att[((size_t)b * S_ + qg) * D_ + h * DK_ + tx * 4] = o;
    }
}

// ---------------------------------------------------------------------------
extern "C" void kernel_launch(void* const* d_in, const int* in_sizes, int n_in,
                              void* d_out, int out_size)
{
    const float* query = (const float*)d_in[0];
    const float* key   = (const float*)d_in[1];
    const float* value = (const float*)d_in[2];
    const int*   mask  = (const int*)  d_in[3];
    const float* gprob = (const float*)d_in[4];
    const float* Wq = (const float*)d_in[5];
    const float* bq = (const float*)d_in[6];
    const float* Wk = (const float*)d_in[7];
    const float* bk = (const float*)d_in[8];
    const float* Wv = (const float*)d_in[9];
    const float* bv = (const float*)d_in[10];
    const float* Wo = (const float*)d_in[11];
    const float* bo = (const float*)d_in[12];
    float* out = (float*)d_out;

    float *qp, *kp, *vp, *ap;
    cudaGetSymbolAddress((void**)&qp, g_q);
    cudaGetSymbolAddress((void**)&kp, g_k);
    cudaGetSymbolAddress((void**)&vp, g_v);
    cudaGetSymbolAddress((void**)&ap, g_att);

    cudaFuncSetAttribute(attn_kernel,
                         cudaFuncAttributeMaxDynamicSharedMemorySize, ATTN_SMEM);
    cudaFuncSetAttribute(qkv_gemm,
                         cudaFuncAttributeMaxDynamicSharedMemorySize, GEMM_SMEM);
    cudaFuncSetAttribute(out_gemm,
                         cudaFuncAttributeMaxDynamicSharedMemorySize, GEMM_SMEM);

    dim3 gqkv(GN / BN_, GM / BM_, 3);
    qkv_gemm<<<gqkv, 256, GEMM_SMEM>>>(query, key, value,
                                       Wq, Wk, Wv, bq, bk, bv,
                                       qp, kp, vp);

    attn_kernel<<<dim3(S_ / BQ, B_ * H_), 256, ATTN_SMEM>>>(
        qp, kp, vp, mask, gprob, ap);

    out_gemm<<<dim3(GN / BN_, GM / BM_), 256, GEMM_SMEM>>>(ap, Wo, bo, out);
}

// round 5
// speedup vs baseline: 1.9895x; 1.1236x over previous
#include <cuda_runtime.h>
#include <cuda_bf16.h>
#include <math.h>
#include <stdint.h>

// Problem constants
#define B_   4
#define S_   1024
#define D_   1024
#define H_   16
#define DK_  64

#define GM   4096
#define GN   1024
#define GK   1024

// bf16x3 GEMM tiling
#define BM_  128
#define BN_  128
#define BK_  32
#define SB   40
#define PF   (BM_ * SB)
#define GEMM_SMEM (2 * 4 * PF * 2)

#define LOG2E 1.4426950408889634f

// Scratch (allocation-free rule: __device__ globals)
__device__ __nv_bfloat16 g_qh[B_ * H_ * S_ * DK_];
__device__ __nv_bfloat16 g_ql[B_ * H_ * S_ * DK_];
__device__ __nv_bfloat16 g_kh[B_ * H_ * S_ * DK_];
__device__ __nv_bfloat16 g_kl[B_ * H_ * S_ * DK_];
__device__ __nv_bfloat16 g_vh[B_ * H_ * S_ * DK_];
__device__ __nv_bfloat16 g_vl[B_ * H_ * S_ * DK_];
__device__ float g_att[B_ * S_ * D_];

// ---------------------------------------------------------------------------
// bf16 helpers
// ---------------------------------------------------------------------------
__device__ __forceinline__ uint32_t packbf2(float lo_e, float hi_e) {
    uint32_t r;
    asm("cvt.rn.bf16x2.f32 %0, %1, %2;" : "=r"(r) : "f"(hi_e), "f"(lo_e));
    return r;
}

__device__ __forceinline__ void split2(float x0, float x1,
                                       uint32_t& hp, uint32_t& lp) {
    hp = packbf2(x0, x1);
    float h0 = __uint_as_float(hp << 16);
    float h1 = __uint_as_float(hp & 0xffff0000u);
    lp = packbf2(x0 - h0, x1 - h1);
}

__device__ __forceinline__ void split_store16(
    __nv_bfloat16* __restrict__ hiP, __nv_bfloat16* __restrict__ loP,
    int idx, const float4* v)
{
    uint32_t h[8], l[8];
#pragma unroll
    for (int i = 0; i < 4; ++i) {
        split2(v[i].x, v[i].y, h[2 * i], l[2 * i]);
        split2(v[i].z, v[i].w, h[2 * i + 1], l[2 * i + 1]);
    }
    *(uint4*)&hiP[idx]     = make_uint4(h[0], h[1], h[2], h[3]);
    *(uint4*)&hiP[idx + 8] = make_uint4(h[4], h[5], h[6], h[7]);
    *(uint4*)&loP[idx]     = make_uint4(l[0], l[1], l[2], l[3]);
    *(uint4*)&loP[idx + 8] = make_uint4(l[4], l[5], l[6], l[7]);
}

__device__ __forceinline__ void mma_bf16(
    float c[4], uint32_t a0, uint32_t a1, uint32_t a2, uint32_t a3,
    uint32_t b0, uint32_t b1)
{
    asm volatile(
        "mma.sync.aligned.m16n8k16.row.col.f32.bf16.bf16.f32 "
        "{%0,%1,%2,%3}, {%4,%5,%6,%7}, {%8,%9}, {%0,%1,%2,%3};\n"
        : "+f"(c[0]), "+f"(c[1]), "+f"(c[2]), "+f"(c[3])
        : "r"(a0), "r"(a1), "r"(a2), "r"(a3), "r"(b0), "r"(b1));
}

// FFMA-only 2^x for x <= 0 (clamped at -120): rint + deg-5 poly + exponent bits
__device__ __forceinline__ float fexp2(float x) {
    x = fmaxf(x, -120.f);
    float r = rintf(x);
    float f = x - r;
    float p = 1.3333558146e-3f;
    p = fmaf(p, f, 9.6181291076e-3f);
    p = fmaf(p, f, 5.5504108664e-2f);
    p = fmaf(p, f, 2.4022650696e-1f);
    p = fmaf(p, f, 6.9314718056e-1f);
    p = fmaf(p, f, 1.0f);
    float s = __int_as_float(((int)r + 127) << 23);
    return p * s;
}

// ---------------------------------------------------------------------------
// bf16x3 GEMM body: out = A @ W^T + bias.
// mode 0: f32 [M,N] row-major.  mode 1: bf16 hi/lo scatter to [B*H, S, DK],
// values scaled by `scale` (1/sqrt(dk) folded into Q).
// ---------------------------------------------------------------------------
__device__ __forceinline__ void gemm_bf16_body(
    const float* __restrict__ A, const float* __restrict__ W,
    const float* __restrict__ bias, float* __restrict__ outF,
    __nv_bfloat16* __restrict__ outH, __nv_bfloat16* __restrict__ outL,
    float scale, int mode)
{
    extern __shared__ __align__(16) char smemRaw[];
    __nv_bfloat16* base = (__nv_bfloat16*)smemRaw;

    const int tid  = threadIdx.x;
    const int lane = tid & 31;
    const int warp = tid >> 5;
    const int wm   = warp & 1;
    const int wn   = warp >> 1;
    const int g    = lane >> 2;
    const int t    = lane & 3;

    const int m0 = blockIdx.y * BM_;
    const int n0 = blockIdx.x * BN_;

    const int r     = tid >> 1;
    const int cHalf = (tid & 1) * 16;

    const float* Aptr = A + (size_t)(m0 + r) * GK + cHalf;
    const float* Wptr = W + (size_t)(n0 + r) * GK + cHalf;

    float c[4][4][4];
#pragma unroll
    for (int i = 0; i < 4; ++i)
#pragma unroll
        for (int j = 0; j < 4; ++j)
#pragma unroll
            for (int e = 0; e < 4; ++e) c[i][j][e] = 0.f;

    const int KT = GK / BK_;
    const int stIdx = r * SB + cHalf;

    float4 aR[4], wR[4];
#pragma unroll
    for (int i = 0; i < 4; ++i) {
        aR[i] = *(const float4*)(Aptr + 4 * i);
        wR[i] = *(const float4*)(Wptr + 4 * i);
    }
    split_store16(base + 0 * PF, base + 1 * PF, stIdx, aR);
    split_store16(base + 2 * PF, base + 3 * PF, stIdx, wR);
#pragma unroll
    for (int i = 0; i < 4; ++i) {
        aR[i] = *(const float4*)(Aptr + BK_ + 4 * i);
        wR[i] = *(const float4*)(Wptr + BK_ + 4 * i);
    }
    __syncthreads();

    int p = 0;
    for (int tt = 0; tt < KT; ++tt) {
        if (tt + 1 < KT) {
            __nv_bfloat16* nb = base + (p ^ 1) * 4 * PF;
            split_store16(nb + 0 * PF, nb + 1 * PF, stIdx, aR);
            split_store16(nb + 2 * PF, nb + 3 * PF, stIdx, wR);
            if (tt + 2 < KT) {
                const int off = (tt + 2) * BK_;
#pragma unroll
                for (int i = 0; i < 4; ++i) {
                    aR[i] = *(const float4*)(Aptr + off + 4 * i);
                    wR[i] = *(const float4*)(Wptr + off + 4 * i);
                }
            }
        }

        const __nv_bfloat16* Ah = base + p * 4 * PF;
        const __nv_bfloat16* Al = Ah + PF;
        const __nv_bfloat16* Wh = Ah + 2 * PF;
        const __nv_bfloat16* Wl = Ah + 3 * PF;

#pragma unroll
        for (int kk = 0; kk < BK_; kk += 16) {
            uint32_t ahi[4][4], alo[4][4], bhi[4][2], blo[4][2];
#pragma unroll
            for (int mi = 0; mi < 4; ++mi) {
                const int ar = wm * 64 + mi * 16 + g;
                const int i00 = ar * SB + kk + t * 2;
                const int i10 = (ar + 8) * SB + kk + t * 2;
                ahi[mi][0] = *(const uint32_t*)&Ah[i00];
                ahi[mi][1] = *(const uint32_t*)&Ah[i10];
                ahi[mi][2] = *(const uint32_t*)&Ah[i00 + 8];
                ahi[mi][3] = *(const uint32_t*)&Ah[i10 + 8];
                alo[mi][0] = *(const uint32_t*)&Al[i00];
                alo[mi][1] = *(const uint32_t*)&Al[i10];
                alo[mi][2] = *(const uint32_t*)&Al[i00 + 8];
                alo[mi][3] = *(const uint32_t*)&Al[i10 + 8];
            }
#pragma unroll
            for (int ni = 0; ni < 4; ++ni) {
                const int br = wn * 32 + ni * 8 + g;
                const int i0 = br * SB + kk + t * 2;
                bhi[ni][0] = *(const uint32_t*)&Wh[i0];
                bhi[ni][1] = *(const uint32_t*)&Wh[i0 + 8];
                blo[ni][0] = *(const uint32_t*)&Wl[i0];
                blo[ni][1] = *(const uint32_t*)&Wl[i0 + 8];
            }
#pragma unroll
            for (int mi = 0; mi < 4; ++mi)
#pragma unroll
                for (int ni = 0; ni < 4; ++ni) {
                    mma_bf16(c[mi][ni], ahi[mi][0], ahi[mi][1], ahi[mi][2], ahi[mi][3],
                             bhi[ni][0], bhi[ni][1]);
                    mma_bf16(c[mi][ni], ahi[mi][0], ahi[mi][1], ahi[mi][2], ahi[mi][3],
                             blo[ni][0], blo[ni][1]);
                    mma_bf16(c[mi][ni], alo[mi][0], alo[mi][1], alo[mi][2], alo[mi][3],
                             bhi[ni][0], bhi[ni][1]);
                }
        }
        __syncthreads();
        p ^= 1;
    }

#pragma unroll
    for (int mi = 0; mi < 4; ++mi) {
        const int row0 = m0 + wm * 64 + mi * 16 + g;
        const int row1 = row0 + 8;
#pragma unroll
        for (int ni = 0; ni < 4; ++ni) {
            const int col = n0 + wn * 32 + ni * 8 + t * 2;
            const float b0v = bias[col], b1v = bias[col + 1];
            if (mode == 0) {
                float2 o0 = {c[mi][ni][0] + b0v, c[mi][ni][1] + b1v};
                float2 o1 = {c[mi][ni][2] + b0v, c[mi][ni][3] + b1v};
                *(float2*)&outF[(size_t)row0 * GN + col] = o0;
                *(float2*)&outF[(size_t)row1 * GN + col] = o1;
            } else {
                const int h  = col >> 6, dk = col & (DK_ - 1);
                const int b0r = row0 >> 10, s0 = row0 & (S_ - 1);
                const int b1r = row1 >> 10, s1 = row1 & (S_ - 1);
                const size_t i0 = (((size_t)(b0r * H_ + h)) * S_ + s0) * DK_ + dk;
                const size_t i1 = (((size_t)(b1r * H_ + h)) * S_ + s1) * DK_ + dk;
                uint32_t hp, lp;
                split2((c[mi][ni][0] + b0v) * scale, (c[mi][ni][1] + b1v) * scale, hp, lp);
                *(uint32_t*)&outH[i0] = hp;
                *(uint32_t*)&outL[i0] = lp;
                split2((c[mi][ni][2] + b0v) * scale, (c[mi][ni][3] + b1v) * scale, hp, lp);
                *(uint32_t*)&outH[i1] = hp;
                *(uint32_t*)&outL[i1] = lp;
            }
        }
    }
}

__global__ __launch_bounds__(256) void qkv_gemm(
    const float* __restrict__ x0, const float* __restrict__ x1, const float* __restrict__ x2,
    const float* __restrict__ W0, const float* __restrict__ W1, const float* __restrict__ W2,
    const float* __restrict__ b0, const float* __restrict__ b1, const float* __restrict__ b2,
    __nv_bfloat16* qh, __nv_bfloat16* ql,
    __nv_bfloat16* kh, __nv_bfloat16* kl,
    __nv_bfloat16* vh, __nv_bfloat16* vl)
{
    const float* A; const float* W; const float* bi;
    __nv_bfloat16 *oh, *ol; float sc;
    if (blockIdx.z == 0)      { A = x0; W = W0; bi = b0; oh = qh; ol = ql; sc = 0.125f; }
    else if (blockIdx.z == 1) { A = x1; W = W1; bi = b1; oh = kh; ol = kl; sc = 1.f; }
    else                      { A = x2; W = W2; bi = b2; oh = vh; ol = vl; sc = 1.f; }
    gemm_bf16_body(A, W, bi, nullptr, oh, ol, sc, 1);
}

__global__ __launch_bounds__(256) void out_gemm(
    const float* __restrict__ A, const float* __restrict__ W,
    const float* __restrict__ bias, float* __restrict__ out)
{
    gemm_bf16_body(A, W, bias, out, nullptr, nullptr, 1.f, 0);
}

// ---------------------------------------------------------------------------
// Tensor-core flash attention, bf16x3 for QK^T and PV, FFMA-based exp.
// 128 threads = 4 warps; each warp owns 16 q rows of a 64-row q tile.
// ---------------------------------------------------------------------------
__global__ __launch_bounds__(128) void attn_kernel(
    const __nv_bfloat16* __restrict__ qh, const __nv_bfloat16* __restrict__ ql,
    const __nv_bfloat16* __restrict__ kh, const __nv_bfloat16* __restrict__ kl,
    const __nv_bfloat16* __restrict__ vh, const __nv_bfloat16* __restrict__ vl,
    const int* __restrict__ mask, const float* __restrict__ gp,
    float* __restrict__ att)
{
    __shared__ __align__(16) uint32_t Khs32[64 * 36];
    __shared__ __align__(16) uint32_t Kls32[64 * 36];
    __shared__ __align__(16) __nv_bfloat16 VThs[64 * 66];
    __shared__ __align__(16) __nv_bfloat16 VTls[64 * 66];

    const int tid  = threadIdx.x;
    const int lane = tid & 31;
    const int warp = tid >> 5;      // 0..3
    const int g    = lane >> 2;     // 0..7
    const int t    = lane & 3;      // 0..3

    const int bh = blockIdx.y;
    const int b  = bh >> 4;
    const int h  = bh & 15;
    const int q0 = blockIdx.x * 64;

    const int qr0 = q0 + warp * 16 + g;   // rows for c0,c1
    const int qr1 = qr0 + 8;              // rows for c2,c3

    const __nv_bfloat16* qhB = qh + (size_t)bh * S_ * DK_;
    const __nv_bfloat16* qlB = ql + (size_t)bh * S_ * DK_;
    const __nv_bfloat16* khB = kh + (size_t)bh * S_ * DK_;
    const __nv_bfloat16* klB = kl + (size_t)bh * S_ * DK_;
    const __nv_bfloat16* vhB = vh + (size_t)bh * S_ * DK_;
    const __nv_bfloat16* vlB = vl + (size_t)bh * S_ * DK_;
    const int*   maskB = mask + (size_t)b * S_ * S_;
    const float* gpB   = gp   + (size_t)b * S_ * S_;

    // Q fragments (held for entire kernel)
    uint32_t aQh[4][4], aQl[4][4];
#pragma unroll
    for (int kc = 0; kc < 4; ++kc) {
        const int col = kc * 16 + 2 * t;
        aQh[kc][0] = *(const uint32_t*)&qhB[qr0 * DK_ + col];
        aQh[kc][1] = *(const uint32_t*)&qhB[qr1 * DK_ + col];
        aQh[kc][2] = *(const uint32_t*)&qhB[qr0 * DK_ + col + 8];
        aQh[kc][3] = *(const uint32_t*)&qhB[qr1 * DK_ + col + 8];
        aQl[kc][0] = *(const uint32_t*)&qlB[qr0 * DK_ + col];
        aQl[kc][1] = *(const uint32_t*)&qlB[qr1 * DK_ + col];
        aQl[kc][2] = *(const uint32_t*)&qlB[qr0 * DK_ + col + 8];
        aQl[kc][3] = *(const uint32_t*)&qlB[qr1 * DK_ + col + 8];
    }

    float acc[8][4];
#pragma unroll
    for (int n = 0; n < 8; ++n)
#pragma unroll
        for (int e = 0; e < 4; ++e) acc[n][e] = 0.f;
    float m0v = -1e30f, m1v = -1e30f, l0 = 0.f, l1 = 0.f;

    for (int kt = 0; kt < S_; kt += 64) {
        __syncthreads();
        // fill K (direct) and V (transposed) hi/lo tiles
#pragma unroll
        for (int i = 0; i < 16; ++i) {
            const int lin = tid + i * 128;
            const int row = lin >> 5;
            const int cu  = lin & 31;
            Khs32[row * 36 + cu] = *(const uint32_t*)&khB[(kt + row) * DK_ + cu * 2];
            Kls32[row * 36 + cu] = *(const uint32_t*)&klB[(kt + row) * DK_ + cu * 2];
            uint32_t v2 = *(const uint32_t*)&vhB[(kt + row) * DK_ + cu * 2];
            VThs[(2 * cu) * 66 + row]     = __ushort_as_bfloat16((unsigned short)(v2 & 0xffff));
            VThs[(2 * cu + 1) * 66 + row] = __ushort_as_bfloat16((unsigned short)(v2 >> 16));
            v2 = *(const uint32_t*)&vlB[(kt + row) * DK_ + cu * 2];
            VTls[(2 * cu) * 66 + row]     = __ushort_as_bfloat16((unsigned short)(v2 & 0xffff));
            VTls[(2 * cu + 1) * 66 + row] = __ushort_as_bfloat16((unsigned short)(v2 >> 16));
        }
        __syncthreads();

        // scores
        float cS[8][4];
#pragma unroll
        for (int n = 0; n < 8; ++n)
#pragma unroll
            for (int e = 0; e < 4; ++e) cS[n][e] = 0.f;

#pragma unroll
        for (int kc = 0; kc < 4; ++kc)
#pragma unroll
            for (int n = 0; n < 8; ++n) {
                const int ridx = (n * 8 + g) * 36 + kc * 8 + t;
                const uint32_t kh0 = Khs32[ridx], kh1 = Khs32[ridx + 4];
                const uint32_t kl0 = Kls32[ridx], kl1 = Kls32[ridx + 4];
                mma_bf16(cS[n], aQh[kc][0], aQh[kc][1], aQh[kc][2], aQh[kc][3], kh0, kh1);
                mma_bf16(cS[n], aQh[kc][0], aQh[kc][1], aQh[kc][2], aQh[kc][3], kl0, kl1);
                mma_bf16(cS[n], aQl[kc][0], aQl[kc][1], aQl[kc][2], aQl[kc][3], kh0, kh1);
            }

        // mask + gp
        float gpr[8][4];
#pragma unroll
        for (int n = 0; n < 8; ++n) {
            const int kcol = kt + n * 8 + 2 * t;
            const int2   mv0 = *(const int2*)&maskB[(size_t)qr0 * S_ + kcol];
            const int2   mv1 = *(const int2*)&maskB[(size_t)qr1 * S_ + kcol];
            const float2 g0  = *(const float2*)&gpB[(size_t)qr0 * S_ + kcol];
            const float2 g1  = *(const float2*)&gpB[(size_t)qr1 * S_ + kcol];
            cS[n][0] = (mv0.x != 0 || qr0 == kcol)     ? cS[n][0] : -1e9f;
            cS[n][1] = (mv0.y != 0 || qr0 == kcol + 1) ? cS[n][1] : -1e9f;
            cS[n][2] = (mv1.x != 0 || qr1 == kcol)     ? cS[n][2] : -1e9f;
            cS[n][3] = (mv1.y != 0 || qr1 == kcol + 1) ? cS[n][3] : -1e9f;
            gpr[n][0] = g0.x; gpr[n][1] = g0.y; gpr[n][2] = g1.x; gpr[n][3] = g1.y;
        }

        // row max
        float mx0 = -1e30f, mx1 = -1e30f;
#pragma unroll
        for (int n = 0; n < 8; ++n) {
            mx0 = fmaxf(mx0, fmaxf(cS[n][0], cS[n][1]));
            mx1 = fmaxf(mx1, fmaxf(cS[n][2], cS[n][3]));
        }
        mx0 = fmaxf(mx0, __shfl_xor_sync(0xffffffffu, mx0, 1));
        mx0 = fmaxf(mx0, __shfl_xor_sync(0xffffffffu, mx0, 2));
        mx1 = fmaxf(mx1, __shfl_xor_sync(0xffffffffu, mx1, 1));
        mx1 = fmaxf(mx1, __shfl_xor_sync(0xffffffffu, mx1, 2));

        const float nm0 = fmaxf(m0v, mx0);
        const float nm1 = fmaxf(m1v, mx1);
        const float corr0 = fexp2((m0v - nm0) * LOG2E);
        const float corr1 = fexp2((m1v - nm1) * LOG2E);
        m0v = nm0; m1v = nm1;

        // exp + gp, pack P fragments
        uint32_t aPh[4][4], aPl[4][4];
        float s0 = 0.f, s1 = 0.f;
#pragma unroll
        for (int n = 0; n < 8; ++n) {
            const float e0 = fexp2((cS[n][0] - nm0) * LOG2E);
            const float e1 = fexp2((cS[n][1] - nm0) * LOG2E);
            const float e2 = fexp2((cS[n][2] - nm1) * LOG2E);
            const float e3 = fexp2((cS[n][3] - nm1) * LOG2E);
            s0 += e0 + e1;
            s1 += e2 + e3;
            const float p0 = e0 * gpr[n][0], p1 = e1 * gpr[n][1];
            const float p2 = e2 * gpr[n][2], p3 = e3 * gpr[n][3];
            const int kc = n >> 1, sl = (n & 1) * 2;
            split2(p0, p1, aPh[kc][sl + 0], aPl[kc][sl + 0]);
            // careful: slot order = a0 rowg klo, a1 rowg8 klo, a2 rowg khi, a3 rowg8 khi
            split2(p2, p3, aPh[kc][sl + 1], aPl[kc][sl + 1]);
        }
        s0 += __shfl_xor_sync(0xffffffffu, s0, 1);
        s0 += __shfl_xor_sync(0xffffffffu, s0, 2);
        s1 += __shfl_xor_sync(0xffffffffu, s1, 1);
        s1 += __shfl_xor_sync(0xffffffffu, s1, 2);
        l0 = l0 * corr0 + s0;
        l1 = l1 * corr1 + s1;

#pragma unroll
        for (int n = 0; n < 8; ++n) {
            acc[n][0] *= corr0; acc[n][1] *= corr0;
            acc[n][2] *= corr1; acc[n][3] *= corr1;
        }

        // PV
#pragma unroll
        for (int kc = 0; kc < 4; ++kc)
#pragma unroll
            for (int n = 0; n < 8; ++n) {
                const int ridx = (n * 8 + g) * 66 + kc * 16 + 2 * t;
                const uint32_t vh0 = *(const uint32_t*)&VThs[ridx];
                const uint32_t vh1 = *(const uint32_t*)&VThs[ridx + 8];
                const uint32_t vl0 = *(const uint32_t*)&VTls[ridx];
                const uint32_t vl1 = *(const uint32_t*)&VTls[ridx + 8];
                mma_bf16(acc[n], aPh[kc][0], aPh[kc][1], aPh[kc][2], aPh[kc][3], vh0, vh1);
                mma_bf16(acc[n], aPh[kc][0], aPh[kc][1], aPh[kc][2], aPh[kc][3], vl0, vl1);
                mma_bf16(acc[n], aPl[kc][0], aPl[kc][1], aPl[kc][2], aPl[kc][3], vh0, vh1);
            }
    }

    // epilogue
    const float inv0 = 1.0f / l0;
    const float inv1 = 1.0f / l1;
    float* attB = att + (size_t)b * S_ * D_ + h * DK_;
#pragma unroll
    for (int n = 0; n < 8; ++n) {
        const int col = n * 8 + 2 * t;
        float2 o0 = {acc[n][0] * inv0, acc[n][1] * inv0};
        float2 o1 = {acc[n][2] * inv1, acc[n][3] * inv1};
        *(float2*)&attB[(size_t)qr0 * D_ + col] = o0;
        *(float2*)&attB[(size_t)qr1 * D_ + col] = o1;
    }
}

// ---------------------------------------------------------------------------
extern "C" void kernel_launch(void* const* d_in, const int* in_sizes, int n_in,
                              void* d_out, int out_size)
{
    const float* query = (const float*)d_in[0];
    const float* key   = (const float*)d_in[1];
    const float* value = (const float*)d_in[2];
    const int*   mask  = (const int*)  d_in[3];
    const float* gprob = (const float*)d_in[4];
    const float* Wq = (const float*)d_in[5];
    const float* bq = (const float*)d_in[6];
    const float* Wk = (const float*)d_in[7];
    const float* bk = (const float*)d_in[8];
    const float* Wv = (const float*)d_in[9];
    const float* bv = (const float*)d_in[10];
    const float* Wo = (const float*)d_in[11];
    const float* bo = (const float*)d_in[12];
    float* out = (float*)d_out;

    __nv_bfloat16 *qhp, *qlp, *khp, *klp, *vhp, *vlp;
    float* ap;
    cudaGetSymbolAddress((void**)&qhp, g_qh);
    cudaGetSymbolAddress((void**)&qlp, g_ql);
    cudaGetSymbolAddress((void**)&khp, g_kh);
    cudaGetSymbolAddress((void**)&klp, g_kl);
    cudaGetSymbolAddress((void**)&vhp, g_vh);
    cudaGetSymbolAddress((void**)&vlp, g_vl);
    cudaGetSymbolAddress((void**)&ap,  g_att);

    cudaFuncSetAttribute(qkv_gemm,
                         cudaFuncAttributeMaxDynamicSharedMemorySize, GEMM_SMEM);
    cudaFuncSetAttribute(out_gemm,
                         cudaFuncAttributeMaxDynamicSharedMemorySize, GEMM_SMEM);

    dim3 gqkv(GN / BN_, GM / BM_, 3);
    qkv_gemm<<<gqkv, 256, GEMM_SMEM>>>(query, key, value,
                                       Wq, Wk, Wv, bq, bk, bv,
                                       qhp, qlp, khp, klp, vhp, vlp);

    attn_kernel<<<dim3(S_ / 64, B_ * H_), 128>>>(
        qhp, qlp, khp, klp, vhp, vlp, mask, gprob, ap);

    out_gemm<<<dim3(GN / BN_, GM / BM_), 256, GEMM_SMEM>>>(ap, Wo, bo, out);
}

// round 8
// speedup vs baseline: 2.1933x; 1.1024x over previous
#include <cuda_runtime.h>
#include <cuda_bf16.h>
#include <math.h>
#include <stdint.h>

// Problem constants
#define B_   4
#define S_   1024
#define D_   1024
#define H_   16
#define DK_  64

#define GM   4096
#define GN   1024
#define GK   1024

#define LOG2E 1.4426950408889634f

// bf16x3 GEMM tiling: 128x128x32 CTA tile, 512 threads, 16 warps (4x4),
// warp tile 32x32, ldmatrix fragment loads.
#define BK_   32
#define SB    40                      // smem row stride in bf16 (80B = 20 banks)
#define PLANE (128 * SB)              // bf16 elems per plane
#define GEMM_SMEM (2 * 4 * PLANE * 2) // 2 bufs x (Ah,Al,Wh,Wl) x bf16 = 81920B

// Attention tiling
#define ATTN_SMEM 0

// Scratch (allocation-free rule: __device__ globals)
__device__ __nv_bfloat16 g_qh[B_ * H_ * S_ * DK_];
__device__ __nv_bfloat16 g_ql[B_ * H_ * S_ * DK_];
__device__ __nv_bfloat16 g_kh[B_ * H_ * S_ * DK_];
__device__ __nv_bfloat16 g_kl[B_ * H_ * S_ * DK_];
__device__ __nv_bfloat16 g_vh[B_ * H_ * S_ * DK_];
__device__ __nv_bfloat16 g_vl[B_ * H_ * S_ * DK_];
__device__ float g_att[B_ * S_ * D_];

// ---------------------------------------------------------------------------
// helpers
// ---------------------------------------------------------------------------
__device__ __forceinline__ uint32_t smem_u32(const void* p) {
    uint32_t a;
    asm("{ .reg .u64 t; cvta.to.shared.u64 t, %1; cvt.u32.u64 %0, t; }"
        : "=r"(a) : "l"(p));
    return a;
}

__device__ __forceinline__ uint32_t packbf2(float lo_e, float hi_e) {
    uint32_t r;
    asm("cvt.rn.bf16x2.f32 %0, %1, %2;" : "=r"(r) : "f"(hi_e), "f"(lo_e));
    return r;
}

__device__ __forceinline__ void split2(float x0, float x1,
                                       uint32_t& hp, uint32_t& lp) {
    hp = packbf2(x0, x1);
    float h0 = __uint_as_float(hp << 16);
    float h1 = __uint_as_float(hp & 0xffff0000u);
    lp = packbf2(x0 - h0, x1 - h1);
}

// convert 8 floats -> 8 bf16 hi + 8 bf16 lo, store 16B each
__device__ __forceinline__ void split_store8(
    __nv_bfloat16* __restrict__ hiP, __nv_bfloat16* __restrict__ loP,
    int idx, float4 v0, float4 v1)
{
    uint4 h, l;
    split2(v0.x, v0.y, h.x, l.x);
    split2(v0.z, v0.w, h.y, l.y);
    split2(v1.x, v1.y, h.z, l.z);
    split2(v1.z, v1.w, h.w, l.w);
    *(uint4*)&hiP[idx] = h;
    *(uint4*)&loP[idx] = l;
}

__device__ __forceinline__ void mma_bf16(
    float c[4], uint32_t a0, uint32_t a1, uint32_t a2, uint32_t a3,
    uint32_t b0, uint32_t b1)
{
    asm volatile(
        "mma.sync.aligned.m16n8k16.row.col.f32.bf16.bf16.f32 "
        "{%0,%1,%2,%3}, {%4,%5,%6,%7}, {%8,%9}, {%0,%1,%2,%3};\n"
        : "+f"(c[0]), "+f"(c[1]), "+f"(c[2]), "+f"(c[3])
        : "r"(a0), "r"(a1), "r"(a2), "r"(a3), "r"(b0), "r"(b1));
}

__device__ __forceinline__ void ldsm4(
    uint32_t& r0, uint32_t& r1, uint32_t& r2, uint32_t& r3, uint32_t addr)
{
    asm volatile("ldmatrix.sync.aligned.m8n8.x4.shared.b16 {%0,%1,%2,%3}, [%4];"
                 : "=r"(r0), "=r"(r1), "=r"(r2), "=r"(r3) : "r"(addr));
}

// FFMA-only 2^x for x <= 0
__device__ __forceinline__ float fexp2(float x) {
    x = fmaxf(x, -120.f);
    float r = rintf(x);
    float f = x - r;
    float p = 1.3333558146e-3f;
    p = fmaf(p, f, 9.6181291076e-3f);
    p = fmaf(p, f, 5.5504108664e-2f);
    p = fmaf(p, f, 2.4022650696e-1f);
    p = fmaf(p, f, 6.9314718056e-1f);
    p = fmaf(p, f, 1.0f);
    float s = __int_as_float(((int)r + 127) << 23);
    return p * s;
}

// ---------------------------------------------------------------------------
// bf16x3 GEMM body (ldmatrix edition): out = A @ W^T + bias.
// 512 threads, warp tile 32x32, double-buffered smem, 1 sync/tile.
// mode 0: f32 [M,N].  mode 1: bf16 hi/lo scatter to [B*H,S,DK], scaled.
// ---------------------------------------------------------------------------
__device__ __forceinline__ void gemm_bf16_body(
    const float* __restrict__ A, const float* __restrict__ W,
    const float* __restrict__ bias, float* __restrict__ outF,
    __nv_bfloat16* __restrict__ outH, __nv_bfloat16* __restrict__ outL,
    float scale, int mode)
{
    extern __shared__ __align__(16) char smemRaw[];
    __nv_bfloat16* base = (__nv_bfloat16*)smemRaw;
    const uint32_t smb = smem_u32(base);

    const int tid  = threadIdx.x;
    const int lane = tid & 31;
    const int warp = tid >> 5;
    const int wm   = warp & 3;          // 4 m-warps
    const int wn   = warp >> 2;         // 4 n-warps
    const int g    = lane >> 2;
    const int t    = lane & 3;

    const int m0 = blockIdx.y * 128;
    const int n0 = blockIdx.x * 128;

    // staging: 4 threads per row, 8 cols each
    const int r  = tid >> 2;            // 0..127
    const int c0 = (tid & 3) * 8;
    const float* Ap = A + (size_t)(m0 + r) * GK + c0;
    const float* Wp = W + (size_t)(n0 + r) * GK + c0;
    const int stIdx = r * SB + c0;

    float c[2][4][4];
#pragma unroll
    for (int mi = 0; mi < 2; ++mi)
#pragma unroll
        for (int ni = 0; ni < 4; ++ni)
#pragma unroll
            for (int e = 0; e < 4; ++e) c[mi][ni][e] = 0.f;

    const int KT = GK / BK_;            // 32

    // ldmatrix lane addressing (element offsets within a plane)
    const int aRowOff = (wm * 32 + (lane & 15)) * SB + (lane >> 4) * 8;
    const int bRowOff = (wn * 32 + (lane & 7) + (lane >> 4) * 8) * SB
                        + ((lane >> 3) & 1) * 8;

    float4 aR[2], wR[2];
    // regs <- tile 0
    aR[0] = *(const float4*)(Ap);     aR[1] = *(const float4*)(Ap + 4);
    wR[0] = *(const float4*)(Wp);     wR[1] = *(const float4*)(Wp + 4);
    // buf0 <- tile 0
    split_store8(base + 0 * PLANE, base + 1 * PLANE, stIdx, aR[0], aR[1]);
    split_store8(base + 2 * PLANE, base + 3 * PLANE, stIdx, wR[0], wR[1]);
    // regs <- tile 1
    aR[0] = *(const float4*)(Ap + BK_);     aR[1] = *(const float4*)(Ap + BK_ + 4);
    wR[0] = *(const float4*)(Wp + BK_);     wR[1] = *(const float4*)(Wp + BK_ + 4);
    __syncthreads();

    int p = 0;
    for (int tt = 0; tt < KT; ++tt) {
        if (tt + 1 < KT) {
            __nv_bfloat16* nb = base + (p ^ 1) * 4 * PLANE;
            split_store8(nb + 0 * PLANE, nb + 1 * PLANE, stIdx, aR[0], aR[1]);
            split_store8(nb + 2 * PLANE, nb + 3 * PLANE, stIdx, wR[0], wR[1]);
            if (tt + 2 < KT) {
                const int off = (tt + 2) * BK_;
                aR[0] = *(const float4*)(Ap + off);
                aR[1] = *(const float4*)(Ap + off + 4);
                wR[0] = *(const float4*)(Wp + off);
                wR[1] = *(const float4*)(Wp + off + 4);
            }
        }

        const uint32_t bufB = smb + p * (4 * PLANE * 2);   // byte base of buffer
        const uint32_t ah = bufB + 2 * aRowOff;
        const uint32_t al = ah + 2 * PLANE;
        const uint32_t bh = bufB + 2 * (2 * PLANE + bRowOff);
        const uint32_t bl = bh + 2 * PLANE;

#pragma unroll
        for (int kk = 0; kk < BK_; kk += 16) {
            uint32_t Ah[2][4], Al[2][4], Bh[2][4], Bl[2][4];
#pragma unroll
            for (int mi = 0; mi < 2; ++mi) {
                const uint32_t ro = 2 * (mi * 16 * SB + kk);
                ldsm4(Ah[mi][0], Ah[mi][1], Ah[mi][2], Ah[mi][3], ah + ro);
                ldsm4(Al[mi][0], Al[mi][1], Al[mi][2], Al[mi][3], al + ro);
            }
#pragma unroll
            for (int np = 0; np < 2; ++np) {
                const uint32_t ro = 2 * (np * 16 * SB + kk);
                ldsm4(Bh[np][0], Bh[np][1], Bh[np][2], Bh[np][3], bh + ro);
                ldsm4(Bl[np][0], Bl[np][1], Bl[np][2], Bl[np][3], bl + ro);
            }
#pragma unroll
            for (int mi = 0; mi < 2; ++mi)
#pragma unroll
                for (int ni = 0; ni < 4; ++ni) {
                    const int np = ni >> 1, q = (ni & 1) * 2;
                    mma_bf16(c[mi][ni], Ah[mi][0], Ah[mi][1], Ah[mi][2], Ah[mi][3],
                             Bh[np][q], Bh[np][q + 1]);
                    mma_bf16(c[mi][ni], Ah[mi][0], Ah[mi][1], Ah[mi][2], Ah[mi][3],
                             Bl[np][q], Bl[np][q + 1]);
                    mma_bf16(c[mi][ni], Al[mi][0], Al[mi][1], Al[mi][2], Al[mi][3],
                             Bh[np][q], Bh[np][q + 1]);
                }
        }
        __syncthreads();
        p ^= 1;
    }

    // epilogue
#pragma unroll
    for (int mi = 0; mi < 2; ++mi) {
        const int row0 = m0 + wm * 32 + mi * 16 + g;
        const int row1 = row0 + 8;
#pragma unroll
        for (int ni = 0; ni < 4; ++ni) {
            const int col = n0 + wn * 32 + ni * 8 + t * 2;
            const float b0v = bias[col], b1v = bias[col + 1];
            if (mode == 0) {
                float2 o0 = {c[mi][ni][0] + b0v, c[mi][ni][1] + b1v};
                float2 o1 = {c[mi][ni][2] + b0v, c[mi][ni][3] + b1v};
                *(float2*)&outF[(size_t)row0 * GN + col] = o0;
                *(float2*)&outF[(size_t)row1 * GN + col] = o1;
            } else {
                const int h  = col >> 6, dk = col & (DK_ - 1);
                const int b0r = row0 >> 10, s0 = row0 & (S_ - 1);
                const int b1r = row1 >> 10, s1 = row1 & (S_ - 1);
                const size_t i0 = (((size_t)(b0r * H_ + h)) * S_ + s0) * DK_ + dk;
                const size_t i1 = (((size_t)(b1r * H_ + h)) * S_ + s1) * DK_ + dk;
                uint32_t hp, lp;
                split2((c[mi][ni][0] + b0v) * scale, (c[mi][ni][1] + b1v) * scale, hp, lp);
                *(uint32_t*)&outH[i0] = hp;
                *(uint32_t*)&outL[i0] = lp;
                split2((c[mi][ni][2] + b0v) * scale, (c[mi][ni][3] + b1v) * scale, hp, lp);
                *(uint32_t*)&outH[i1] = hp;
                *(uint32_t*)&outL[i1] = lp;
            }
        }
    }
}

__global__ __launch_bounds__(512) void qkv_gemm(
    const float* __restrict__ x0, const float* __restrict__ x1, const float* __restrict__ x2,
    const float* __restrict__ W0, const float* __restrict__ W1, const float* __restrict__ W2,
    const float* __restrict__ b0, const float* __restrict__ b1, const float* __restrict__ b2,
    __nv_bfloat16* qh, __nv_bfloat16* ql,
    __nv_bfloat16* kh, __nv_bfloat16* kl,
    __nv_bfloat16* vh, __nv_bfloat16* vl)
{
    const float* A; const float* W; const float* bi;
    __nv_bfloat16 *oh, *ol; float sc;
    if (blockIdx.z == 0)      { A = x0; W = W0; bi = b0; oh = qh; ol = ql; sc = 0.125f; }
    else if (blockIdx.z == 1) { A = x1; W = W1; bi = b1; oh = kh; ol = kl; sc = 1.f; }
    else                      { A = x2; W = W2; bi = b2; oh = vh; ol = vl; sc = 1.f; }
    gemm_bf16_body(A, W, bi, nullptr, oh, ol, sc, 1);
}

__global__ __launch_bounds__(512) void out_gemm(
    const float* __restrict__ A, const float* __restrict__ W,
    const float* __restrict__ bias, float* __restrict__ out)
{
    gemm_bf16_body(A, W, bias, out, nullptr, nullptr, 1.f, 0);
}

// ---------------------------------------------------------------------------
// Tensor-core flash attention (unchanged from Round 5 champion)
// ---------------------------------------------------------------------------
__global__ __launch_bounds__(128) void attn_kernel(
    const __nv_bfloat16* __restrict__ qh, const __nv_bfloat16* __restrict__ ql,
    const __nv_bfloat16* __restrict__ kh, const __nv_bfloat16* __restrict__ kl,
    const __nv_bfloat16* __restrict__ vh, const __nv_bfloat16* __restrict__ vl,
    const int* __restrict__ mask, const float* __restrict__ gp,
    float* __restrict__ att)
{
    __shared__ __align__(16) uint32_t Khs32[64 * 36];
    __shared__ __align__(16) uint32_t Kls32[64 * 36];
    __shared__ __align__(16) __nv_bfloat16 VThs[64 * 66];
    __shared__ __align__(16) __nv_bfloat16 VTls[64 * 66];

    const int tid  = threadIdx.x;
    const int lane = tid & 31;
    const int warp = tid >> 5;
    const int g    = lane >> 2;
    const int t    = lane & 3;

    const int bh = blockIdx.y;
    const int b  = bh >> 4;
    const int h  = bh & 15;
    const int q0 = blockIdx.x * 64;

    const int qr0 = q0 + warp * 16 + g;
    const int qr1 = qr0 + 8;

    const __nv_bfloat16* qhB = qh + (size_t)bh * S_ * DK_;
    const __nv_bfloat16* qlB = ql + (size_t)bh * S_ * DK_;
    const __nv_bfloat16* khB = kh + (size_t)bh * S_ * DK_;
    const __nv_bfloat16* klB = kl + (size_t)bh * S_ * DK_;
    const __nv_bfloat16* vhB = vh + (size_t)bh * S_ * DK_;
    const __nv_bfloat16* vlB = vl + (size_t)bh * S_ * DK_;
    const int*   maskB = mask + (size_t)b * S_ * S_;
    const float* gpB   = gp   + (size_t)b * S_ * S_;

    uint32_t aQh[4][4], aQl[4][4];
#pragma unroll
    for (int kc = 0; kc < 4; ++kc) {
        const int col = kc * 16 + 2 * t;
        aQh[kc][0] = *(const uint32_t*)&qhB[qr0 * DK_ + col];
        aQh[kc][1] = *(const uint32_t*)&qhB[qr1 * DK_ + col];
        aQh[kc][2] = *(const uint32_t*)&qhB[qr0 * DK_ + col + 8];
        aQh[kc][3] = *(const uint32_t*)&qhB[qr1 * DK_ + col + 8];
        aQl[kc][0] = *(const uint32_t*)&qlB[qr0 * DK_ + col];
        aQl[kc][1] = *(const uint32_t*)&qlB[qr1 * DK_ + col];
        aQl[kc][2] = *(const uint32_t*)&qlB[qr0 * DK_ + col + 8];
        aQl[kc][3] = *(const uint32_t*)&qlB[qr1 * DK_ + col + 8];
    }

    float acc[8][4];
#pragma unroll
    for (int n = 0; n < 8; ++n)
#pragma unroll
        for (int e = 0; e < 4; ++e) acc[n][e] = 0.f;
    float m0v = -1e30f, m1v = -1e30f, l0 = 0.f, l1 = 0.f;

    for (int kt = 0; kt < S_; kt += 64) {
        __syncthreads();
#pragma unroll
        for (int i = 0; i < 16; ++i) {
            const int lin = tid + i * 128;
            const int row = lin >> 5;
            const int cu  = lin & 31;
            Khs32[row * 36 + cu] = *(const uint32_t*)&khB[(kt + row) * DK_ + cu * 2];
            Kls32[row * 36 + cu] = *(const uint32_t*)&klB[(kt + row) * DK_ + cu * 2];
            uint32_t v2 = *(const uint32_t*)&vhB[(kt + row) * DK_ + cu * 2];
            VThs[(2 * cu) * 66 + row]     = __ushort_as_bfloat16((unsigned short)(v2 & 0xffff));
            VThs[(2 * cu + 1) * 66 + row] = __ushort_as_bfloat16((unsigned short)(v2 >> 16));
            v2 = *(const uint32_t*)&vlB[(kt + row) * DK_ + cu * 2];
            VTls[(2 * cu) * 66 + row]     = __ushort_as_bfloat16((unsigned short)(v2 & 0xffff));
            VTls[(2 * cu + 1) * 66 + row] = __ushort_as_bfloat16((unsigned short)(v2 >> 16));
        }
        __syncthreads();

        float cS[8][4];
#pragma unroll
        for (int n = 0; n < 8; ++n)
#pragma unroll
            for (int e = 0; e < 4; ++e) cS[n][e] = 0.f;

#pragma unroll
        for (int kc = 0; kc < 4; ++kc)
#pragma unroll
            for (int n = 0; n < 8; ++n) {
                const int ridx = (n * 8 + g) * 36 + kc * 8 + t;
                const uint32_t kh0 = Khs32[ridx], kh1 = Khs32[ridx + 4];
                const uint32_t kl0 = Kls32[ridx], kl1 = Kls32[ridx + 4];
                mma_bf16(cS[n], aQh[kc][0], aQh[kc][1], aQh[kc][2], aQh[kc][3], kh0, kh1);
                mma_bf16(cS[n], aQh[kc][0], aQh[kc][1], aQh[kc][2], aQh[kc][3], kl0, kl1);
                mma_bf16(cS[n], aQl[kc][0], aQl[kc][1], aQl[kc][2], aQl[kc][3], kh0, kh1);
            }

        float gpr[8][4];
#pragma unroll
        for (int n = 0; n < 8; ++n) {
            const int kcol = kt + n * 8 + 2 * t;
            const int2   mv0 = *(const int2*)&maskB[(size_t)qr0 * S_ + kcol];
            const int2   mv1 = *(const int2*)&maskB[(size_t)qr1 * S_ + kcol];
            const float2 g0  = *(const float2*)&gpB[(size_t)qr0 * S_ + kcol];
            const float2 g1  = *(const float2*)&gpB[(size_t)qr1 * S_ + kcol];
            cS[n][0] = (mv0.x != 0 || qr0 == kcol)     ? cS[n][0] : -1e9f;
            cS[n][1] = (mv0.y != 0 || qr0 == kcol + 1) ? cS[n][1] : -1e9f;
            cS[n][2] = (mv1.x != 0 || qr1 == kcol)     ? cS[n][2] : -1e9f;
            cS[n][3] = (mv1.y != 0 || qr1 == kcol + 1) ? cS[n][3] : -1e9f;
            gpr[n][0] = g0.x; gpr[n][1] = g0.y; gpr[n][2] = g1.x; gpr[n][3] = g1.y;
        }

        float mx0 = -1e30f, mx1 = -1e30f;
#pragma unroll
        for (int n = 0; n < 8; ++n) {
            mx0 = fmaxf(mx0, fmaxf(cS[n][0], cS[n][1]));
            mx1 = fmaxf(mx1, fmaxf(cS[n][2], cS[n][3]));
        }
        mx0 = fmaxf(mx0, __shfl_xor_sync(0xffffffffu, mx0, 1));
        mx0 = fmaxf(mx0, __shfl_xor_sync(0xffffffffu, mx0, 2));
        mx1 = fmaxf(mx1, __shfl_xor_sync(0xffffffffu, mx1, 1));
        mx1 = fmaxf(mx1, __shfl_xor_sync(0xffffffffu, mx1, 2));

        const float nm0 = fmaxf(m0v, mx0);
        const float nm1 = fmaxf(m1v, mx1);
        const float corr0 = fexp2((m0v - nm0) * LOG2E);
        const float corr1 = fexp2((m1v - nm1) * LOG2E);
        m0v = nm0; m1v = nm1;

        uint32_t aPh[4][4], aPl[4][4];
        float s0 = 0.f, s1 = 0.f;
#pragma unroll
        for (int n = 0; n < 8; ++n) {
            const float e0 = fexp2((cS[n][0] - nm0) * LOG2E);
            const float e1 = fexp2((cS[n][1] - nm0) * LOG2E);
            const float e2 = fexp2((cS[n][2] - nm1) * LOG2E);
            const float e3 = fexp2((cS[n][3] - nm1) * LOG2E);
            s0 += e0 + e1;
            s1 += e2 + e3;
            const float p0 = e0 * gpr[n][0], p1 = e1 * gpr[n][1];
            const float p2 = e2 * gpr[n][2], p3 = e3 * gpr[n][3];
            const int kc = n >> 1, sl = (n & 1) * 2;
            split2(p0, p1, aPh[kc][sl + 0], aPl[kc][sl + 0]);
            split2(p2, p3, aPh[kc][sl + 1], aPl[kc][sl + 1]);
        }
        s0 += __shfl_xor_sync(0xffffffffu, s0, 1);
        s0 += __shfl_xor_sync(0xffffffffu, s0, 2);
        s1 += __shfl_xor_sync(0xffffffffu, s1, 1);
        s1 += __shfl_xor_sync(0xffffffffu, s1, 2);
        l0 = l0 * corr0 + s0;
        l1 = l1 * corr1 + s1;

#pragma unroll
        for (int n = 0; n < 8; ++n) {
            acc[n][0] *= corr0; acc[n][1] *= corr0;
            acc[n][2] *= corr1; acc[n][3] *= corr1;
        }

#pragma unroll
        for (int kc = 0; kc < 4; ++kc)
#pragma unroll
            for (int n = 0; n < 8; ++n) {
                const int ridx = (n * 8 + g) * 66 + kc * 16 + 2 * t;
                const uint32_t vh0 = *(const uint32_t*)&VThs[ridx];
                const uint32_t vh1 = *(const uint32_t*)&VThs[ridx + 8];
                const uint32_t vl0 = *(const uint32_t*)&VTls[ridx];
                const uint32_t vl1 = *(const uint32_t*)&VTls[ridx + 8];
                mma_bf16(acc[n], aPh[kc][0], aPh[kc][1], aPh[kc][2], aPh[kc][3], vh0, vh1);
                mma_bf16(acc[n], aPh[kc][0], aPh[kc][1], aPh[kc][2], aPh[kc][3], vl0, vl1);
                mma_bf16(acc[n], aPl[kc][0], aPl[kc][1], aPl[kc][2], aPl[kc][3], vh0, vh1);
            }
    }

    const float inv0 = 1.0f / l0;
    const float inv1 = 1.0f / l1;
    float* attB = att + (size_t)b * S_ * D_ + h * DK_;
#pragma unroll
    for (int n = 0; n < 8; ++n) {
        const int col = n * 8 + 2 * t;
        float2 o0 = {acc[n][0] * inv0, acc[n][1] * inv0};
        float2 o1 = {acc[n][2] * inv1, acc[n][3] * inv1};
        *(float2*)&attB[(size_t)qr0 * D_ + col] = o0;
        *(float2*)&attB[(size_t)qr1 * D_ + col] = o1;
    }
}

// ---------------------------------------------------------------------------
extern "C" void kernel_launch(void* const* d_in, const int* in_sizes, int n_in,
                              void* d_out, int out_size)
{
    const float* query = (const float*)d_in[0];
    const float* key   = (const float*)d_in[1];
    const float* value = (const float*)d_in[2];
    const int*   mask  = (const int*)  d_in[3];
    const float* gprob = (const float*)d_in[4];
    const float* Wq = (const float*)d_in[5];
    const float* bq = (const float*)d_in[6];
    const float* Wk = (const float*)d_in[7];
    const float* bk = (const float*)d_in[8];
    const float* Wv = (const float*)d_in[9];
    const float* bv = (const float*)d_in[10];
    const float* Wo = (const float*)d_in[11];
    const float* bo = (const float*)d_in[12];
    float* out = (float*)d_out;

    __nv_bfloat16 *qhp, *qlp, *khp, *klp, *vhp, *vlp;
    float* ap;
    cudaGetSymbolAddress((void**)&qhp, g_qh);
    cudaGetSymbolAddress((void**)&qlp, g_ql);
    cudaGetSymbolAddress((void**)&khp, g_kh);
    cudaGetSymbolAddress((void**)&klp, g_kl);
    cudaGetSymbolAddress((void**)&vhp, g_vh);
    cudaGetSymbolAddress((void**)&vlp, g_vl);
    cudaGetSymbolAddress((void**)&ap,  g_att);

    cudaFuncSetAttribute(qkv_gemm,
                         cudaFuncAttributeMaxDynamicSharedMemorySize, GEMM_SMEM);
    cudaFuncSetAttribute(out_gemm,
                         cudaFuncAttributeMaxDynamicSharedMemorySize, GEMM_SMEM);

    dim3 gqkv(GN / 128, GM / 128, 3);
    qkv_gemm<<<gqkv, 512, GEMM_SMEM>>>(query, key, value,
                                       Wq, Wk, Wv, bq, bk, bv,
                                       qhp, qlp, khp, klp, vhp, vlp);

    attn_kernel<<<dim3(S_ / 64, B_ * H_), 128>>>(
        qhp, qlp, khp, klp, vhp, vlp, mask, gprob, ap);

    out_gemm<<<dim3(GN / 128, GM / 128), 512, GEMM_SMEM>>>(ap, Wo, bo, out);
}

// round 9
// speedup vs baseline: 4.4773x; 2.0414x over previous
#include <cuda_runtime.h>
#include <cuda_fp16.h>
#include <math.h>
#include <stdint.h>

// Problem constants
#define B_   4
#define S_   1024
#define D_   1024
#define H_   16
#define DK_  64

#define GM   4096
#define GN   1024
#define GK   1024

#define LOG2E 1.4426950408889634f

// fp16 GEMM tiling: 128x128x32 CTA tile, 512 threads, 16 warps (4x4),
// warp tile 32x32, ldmatrix fragment loads, plain fp16 operands (fp32 accum).
#define BK_   32
#define SB    40                      // smem row stride in fp16 (80B = 20 banks)
#define PLANE (128 * SB)              // fp16 elems per plane (5120)
#define GEMM_SMEM (2 * 2 * PLANE * 2) // 2 bufs x (Ah,Bh) x fp16 = 40960B

// Scratch (allocation-free rule: __device__ globals)
__device__ __half g_q[B_ * H_ * S_ * DK_];
__device__ __half g_k[B_ * H_ * S_ * DK_];
__device__ __half g_v[B_ * H_ * S_ * DK_];
__device__ float  g_att[B_ * S_ * D_];

// ---------------------------------------------------------------------------
// helpers
// ---------------------------------------------------------------------------
__device__ __forceinline__ uint32_t smem_u32(const void* p) {
    uint32_t a;
    asm("{ .reg .u64 t; cvta.to.shared.u64 t, %1; cvt.u32.u64 %0, t; }"
        : "=r"(a) : "l"(p));
    return a;
}

// pack two floats into fp16x2 (elem0 -> low half, elem1 -> high half)
__device__ __forceinline__ uint32_t packh2(float e0, float e1) {
    uint32_t r;
    asm("cvt.rn.f16x2.f32 %0, %1, %2;" : "=r"(r) : "f"(e1), "f"(e0));
    return r;
}

__device__ __forceinline__ void mma_f16(
    float c[4], uint32_t a0, uint32_t a1, uint32_t a2, uint32_t a3,
    uint32_t b0, uint32_t b1)
{
    asm volatile(
        "mma.sync.aligned.m16n8k16.row.col.f32.f16.f16.f32 "
        "{%0,%1,%2,%3}, {%4,%5,%6,%7}, {%8,%9}, {%0,%1,%2,%3};\n"
        : "+f"(c[0]), "+f"(c[1]), "+f"(c[2]), "+f"(c[3])
        : "r"(a0), "r"(a1), "r"(a2), "r"(a3), "r"(b0), "r"(b1));
}

__device__ __forceinline__ void ldsm4(
    uint32_t& r0, uint32_t& r1, uint32_t& r2, uint32_t& r3, uint32_t addr)
{
    asm volatile("ldmatrix.sync.aligned.m8n8.x4.shared.b16 {%0,%1,%2,%3}, [%4];"
                 : "=r"(r0), "=r"(r1), "=r"(r2), "=r"(r3) : "r"(addr));
}

// convert 8 floats -> 8 fp16, store 16B
__device__ __forceinline__ void cvt_store8(
    __half* __restrict__ p, int idx, float4 v0, float4 v1)
{
    uint4 h;
    h.x = packh2(v0.x, v0.y);
    h.y = packh2(v0.z, v0.w);
    h.z = packh2(v1.x, v1.y);
    h.w = packh2(v1.z, v1.w);
    *(uint4*)&p[idx] = h;
}

// FFMA-only 2^x for x <= 0
__device__ __forceinline__ float fexp2(float x) {
    x = fmaxf(x, -120.f);
    float r = rintf(x);
    float f = x - r;
    float p = 1.3333558146e-3f;
    p = fmaf(p, f, 9.6181291076e-3f);
    p = fmaf(p, f, 5.5504108664e-2f);
    p = fmaf(p, f, 2.4022650696e-1f);
    p = fmaf(p, f, 6.9314718056e-1f);
    p = fmaf(p, f, 1.0f);
    float s = __int_as_float(((int)r + 127) << 23);
    return p * s;
}

// ---------------------------------------------------------------------------
// fp16 GEMM body: out = A @ W^T + bias.
// 512 threads, warp tile 32x32, double-buffered smem, 1 sync/tile.
// mode 0: f32 [M,N].  mode 1: fp16 scatter to [B*H,S,DK], scaled.
// ---------------------------------------------------------------------------
__device__ __forceinline__ void gemm_f16_body(
    const float* __restrict__ A, const float* __restrict__ W,
    const float* __restrict__ bias, float* __restrict__ outF,
    __half* __restrict__ outH, float scale, int mode)
{
    extern __shared__ __align__(16) char smemRaw[];
    __half* base = (__half*)smemRaw;
    const uint32_t smb = smem_u32(base);

    const int tid  = threadIdx.x;
    const int lane = tid & 31;
    const int warp = tid >> 5;
    const int wm   = warp & 3;          // 4 m-warps
    const int wn   = warp >> 2;         // 4 n-warps
    const int g    = lane >> 2;
    const int t    = lane & 3;

    const int m0 = blockIdx.y * 128;
    const int n0 = blockIdx.x * 128;

    // staging: 4 threads per row, 8 cols each
    const int r  = tid >> 2;            // 0..127
    const int c0 = (tid & 3) * 8;
    const float* Ap = A + (size_t)(m0 + r) * GK + c0;
    const float* Wp = W + (size_t)(n0 + r) * GK + c0;
    const int stIdx = r * SB + c0;

    float c[2][4][4];
#pragma unroll
    for (int mi = 0; mi < 2; ++mi)
#pragma unroll
        for (int ni = 0; ni < 4; ++ni)
#pragma unroll
            for (int e = 0; e < 4; ++e) c[mi][ni][e] = 0.f;

    const int KT = GK / BK_;            // 32

    // ldmatrix lane addressing (fp16 element offsets within a plane)
    const int aRowOff = (wm * 32 + (lane & 15)) * SB + (lane >> 4) * 8;
    const int bRowOff = (wn * 32 + (lane & 7) + (lane >> 4) * 8) * SB
                        + ((lane >> 3) & 1) * 8;

    float4 aR[2], wR[2];
    // regs <- tile 0
    aR[0] = *(const float4*)(Ap);     aR[1] = *(const float4*)(Ap + 4);
    wR[0] = *(const float4*)(Wp);     wR[1] = *(const float4*)(Wp + 4);
    // buf0 <- tile 0
    cvt_store8(base + 0 * PLANE, stIdx, aR[0], aR[1]);
    cvt_store8(base + 1 * PLANE, stIdx, wR[0], wR[1]);
    // regs <- tile 1
    aR[0] = *(const float4*)(Ap + BK_);     aR[1] = *(const float4*)(Ap + BK_ + 4);
    wR[0] = *(const float4*)(Wp + BK_);     wR[1] = *(const float4*)(Wp + BK_ + 4);
    __syncthreads();

    int p = 0;
    for (int tt = 0; tt < KT; ++tt) {
        if (tt + 1 < KT) {
            __half* nb = base + (p ^ 1) * 2 * PLANE;
            cvt_store8(nb + 0 * PLANE, stIdx, aR[0], aR[1]);
            cvt_store8(nb + 1 * PLANE, stIdx, wR[0], wR[1]);
            if (tt + 2 < KT) {
                const int off = (tt + 2) * BK_;
                aR[0] = *(const float4*)(Ap + off);
                aR[1] = *(const float4*)(Ap + off + 4);
                wR[0] = *(const float4*)(Wp + off);
                wR[1] = *(const float4*)(Wp + off + 4);
            }
        }

        const uint32_t bufB = smb + p * (2 * PLANE * 2);   // byte base of buffer
        const uint32_t ah = bufB + 2 * aRowOff;
        const uint32_t bh = bufB + 2 * (PLANE + bRowOff);

#pragma unroll
        for (int kk = 0; kk < BK_; kk += 16) {
            uint32_t Af[2][4], Bf[2][4];
#pragma unroll
            for (int mi = 0; mi < 2; ++mi) {
                const uint32_t ro = 2 * (mi * 16 * SB + kk);
                ldsm4(Af[mi][0], Af[mi][1], Af[mi][2], Af[mi][3], ah + ro);
            }
#pragma unroll
            for (int np = 0; np < 2; ++np) {
                const uint32_t ro = 2 * (np * 16 * SB + kk);
                ldsm4(Bf[np][0], Bf[np][1], Bf[np][2], Bf[np][3], bh + ro);
            }
#pragma unroll
            for (int mi = 0; mi < 2; ++mi)
#pragma unroll
                for (int ni = 0; ni < 4; ++ni) {
                    const int np = ni >> 1, q = (ni & 1) * 2;
                    mma_f16(c[mi][ni], Af[mi][0], Af[mi][1], Af[mi][2], Af[mi][3],
                            Bf[np][q], Bf[np][q + 1]);
                }
        }
        __syncthreads();
        p ^= 1;
    }

    // epilogue
#pragma unroll
    for (int mi = 0; mi < 2; ++mi) {
        const int row0 = m0 + wm * 32 + mi * 16 + g;
        const int row1 = row0 + 8;
#pragma unroll
        for (int ni = 0; ni < 4; ++ni) {
            const int col = n0 + wn * 32 + ni * 8 + t * 2;
            const float b0v = bias[col], b1v = bias[col + 1];
            if (mode == 0) {
                float2 o0 = {c[mi][ni][0] + b0v, c[mi][ni][1] + b1v};
                float2 o1 = {c[mi][ni][2] + b0v, c[mi][ni][3] + b1v};
                *(float2*)&outF[(size_t)row0 * GN + col] = o0;
                *(float2*)&outF[(size_t)row1 * GN + col] = o1;
            } else {
                const int h  = col >> 6, dk = col & (DK_ - 1);
                const int b0r = row0 >> 10, s0 = row0 & (S_ - 1);
                const int b1r = row1 >> 10, s1 = row1 & (S_ - 1);
                const size_t i0 = (((size_t)(b0r * H_ + h)) * S_ + s0) * DK_ + dk;
                const size_t i1 = (((size_t)(b1r * H_ + h)) * S_ + s1) * DK_ + dk;
                *(uint32_t*)&outH[i0] =
                    packh2((c[mi][ni][0] + b0v) * scale, (c[mi][ni][1] + b1v) * scale);
                *(uint32_t*)&outH[i1] =
                    packh2((c[mi][ni][2] + b0v) * scale, (c[mi][ni][3] + b1v) * scale);
            }
        }
    }
}

__global__ __launch_bounds__(512) void qkv_gemm(
    const float* __restrict__ x0, const float* __restrict__ x1, const float* __restrict__ x2,
    const float* __restrict__ W0, const float* __restrict__ W1, const float* __restrict__ W2,
    const float* __restrict__ b0, const float* __restrict__ b1, const float* __restrict__ b2,
    __half* q, __half* k, __half* v)
{
    const float* A; const float* W; const float* bi;
    __half* o; float sc;
    if (blockIdx.z == 0)      { A = x0; W = W0; bi = b0; o = q; sc = 0.125f; }
    else if (blockIdx.z == 1) { A = x1; W = W1; bi = b1; o = k; sc = 1.f; }
    else                      { A = x2; W = W2; bi = b2; o = v; sc = 1.f; }
    gemm_f16_body(A, W, bi, nullptr, o, sc, 1);
}

__global__ __launch_bounds__(512) void out_gemm(
    const float* __restrict__ A, const float* __restrict__ W,
    const float* __restrict__ bias, float* __restrict__ out)
{
    gemm_f16_body(A, W, bias, out, nullptr, 1.f, 0);
}

// ---------------------------------------------------------------------------
// fp16 tensor-core flash attention (FA2-style), FFMA-based exp.
// 128 threads = 4 warps; each warp owns 16 q rows of a 64-row q tile.
// ---------------------------------------------------------------------------
__global__ __launch_bounds__(128) void attn_kernel(
    const __half* __restrict__ q, const __half* __restrict__ k,
    const __half* __restrict__ v,
    const int* __restrict__ mask, const float* __restrict__ gp,
    float* __restrict__ att)
{
    __shared__ __align__(16) uint32_t Khs32[64 * 36];
    __shared__ __align__(16) __half   VThs[64 * 66];

    const int tid  = threadIdx.x;
    const int lane = tid & 31;
    const int warp = tid >> 5;
    const int g    = lane >> 2;
    const int t    = lane & 3;

    const int bh = blockIdx.y;
    const int b  = bh >> 4;
    const int h  = bh & 15;
    const int q0 = blockIdx.x * 64;

    const int qr0 = q0 + warp * 16 + g;
    const int qr1 = qr0 + 8;

    const __half* qB = q + (size_t)bh * S_ * DK_;
    const __half* kB = k + (size_t)bh * S_ * DK_;
    const __half* vB = v + (size_t)bh * S_ * DK_;
    const int*   maskB = mask + (size_t)b * S_ * S_;
    const float* gpB   = gp   + (size_t)b * S_ * S_;

    // Q fragments (held for entire kernel)
    uint32_t aQ[4][4];
#pragma unroll
    for (int kc = 0; kc < 4; ++kc) {
        const int col = kc * 16 + 2 * t;
        aQ[kc][0] = *(const uint32_t*)&qB[qr0 * DK_ + col];
        aQ[kc][1] = *(const uint32_t*)&qB[qr1 * DK_ + col];
        aQ[kc][2] = *(const uint32_t*)&qB[qr0 * DK_ + col + 8];
        aQ[kc][3] = *(const uint32_t*)&qB[qr1 * DK_ + col + 8];
    }

    float acc[8][4];
#pragma unroll
    for (int n = 0; n < 8; ++n)
#pragma unroll
        for (int e = 0; e < 4; ++e) acc[n][e] = 0.f;
    float m0v = -1e30f, m1v = -1e30f, l0 = 0.f, l1 = 0.f;

    for (int kt = 0; kt < S_; kt += 64) {
        __syncthreads();
        // fill K (direct) and V (transposed) tiles
#pragma unroll
        for (int i = 0; i < 16; ++i) {
            const int lin = tid + i * 128;
            const int row = lin >> 5;
            const int cu  = lin & 31;
            Khs32[row * 36 + cu] = *(const uint32_t*)&kB[(kt + row) * DK_ + cu * 2];
            const uint32_t v2 = *(const uint32_t*)&vB[(kt + row) * DK_ + cu * 2];
            VThs[(2 * cu) * 66 + row]     = __ushort_as_half((unsigned short)(v2 & 0xffff));
            VThs[(2 * cu + 1) * 66 + row] = __ushort_as_half((unsigned short)(v2 >> 16));
        }
        __syncthreads();

        // scores
        float cS[8][4];
#pragma unroll
        for (int n = 0; n < 8; ++n)
#pragma unroll
            for (int e = 0; e < 4; ++e) cS[n][e] = 0.f;

#pragma unroll
        for (int kc = 0; kc < 4; ++kc)
#pragma unroll
            for (int n = 0; n < 8; ++n) {
                const int ridx = (n * 8 + g) * 36 + kc * 8 + t;
                mma_f16(cS[n], aQ[kc][0], aQ[kc][1], aQ[kc][2], aQ[kc][3],
                        Khs32[ridx], Khs32[ridx + 4]);
            }

        // mask + gp
        float gpr[8][4];
#pragma unroll
        for (int n = 0; n < 8; ++n) {
            const int kcol = kt + n * 8 + 2 * t;
            const int2   mv0 = *(const int2*)&maskB[(size_t)qr0 * S_ + kcol];
            const int2   mv1 = *(const int2*)&maskB[(size_t)qr1 * S_ + kcol];
            const float2 g0  = *(const float2*)&gpB[(size_t)qr0 * S_ + kcol];
            const float2 g1  = *(const float2*)&gpB[(size_t)qr1 * S_ + kcol];
            cS[n][0] = (mv0.x != 0 || qr0 == kcol)     ? cS[n][0] : -1e9f;
            cS[n][1] = (mv0.y != 0 || qr0 == kcol + 1) ? cS[n][1] : -1e9f;
            cS[n][2] = (mv1.x != 0 || qr1 == kcol)     ? cS[n][2] : -1e9f;
            cS[n][3] = (mv1.y != 0 || qr1 == kcol + 1) ? cS[n][3] : -1e9f;
            gpr[n][0] = g0.x; gpr[n][1] = g0.y; gpr[n][2] = g1.x; gpr[n][3] = g1.y;
        }

        // row max
        float mx0 = -1e30f, mx1 = -1e30f;
#pragma unroll
        for (int n = 0; n < 8; ++n) {
            mx0 = fmaxf(mx0, fmaxf(cS[n][0], cS[n][1]));
            mx1 = fmaxf(mx1, fmaxf(cS[n][2], cS[n][3]));
        }
        mx0 = fmaxf(mx0, __shfl_xor_sync(0xffffffffu, mx0, 1));
        mx0 = fmaxf(mx0, __shfl_xor_sync(0xffffffffu, mx0, 2));
        mx1 = fmaxf(mx1, __shfl_xor_sync(0xffffffffu, mx1, 1));
        mx1 = fmaxf(mx1, __shfl_xor_sync(0xffffffffu, mx1, 2));

        const float nm0 = fmaxf(m0v, mx0);
        const float nm1 = fmaxf(m1v, mx1);
        const float corr0 = fexp2((m0v - nm0) * LOG2E);
        const float corr1 = fexp2((m1v - nm1) * LOG2E);
        m0v = nm0; m1v = nm1;

        // exp + gp, pack P fragments (fp16)
        uint32_t aP[4][4];
        float s0 = 0.f, s1 = 0.f;
#pragma unroll
        for (int n = 0; n < 8; ++n) {
            const float e0 = fexp2((cS[n][0] - nm0) * LOG2E);
            const float e1 = fexp2((cS[n][1] - nm0) * LOG2E);
            const float e2 = fexp2((cS[n][2] - nm1) * LOG2E);
            const float e3 = fexp2((cS[n][3] - nm1) * LOG2E);
            s0 += e0 + e1;
            s1 += e2 + e3;
            const int kc = n >> 1, sl = (n & 1) * 2;
            aP[kc][sl + 0] = packh2(e0 * gpr[n][0], e1 * gpr[n][1]);
            aP[kc][sl + 1] = packh2(e2 * gpr[n][2], e3 * gpr[n][3]);
        }
        s0 += __shfl_xor_sync(0xffffffffu, s0, 1);
        s0 += __shfl_xor_sync(0xffffffffu, s0, 2);
        s1 += __shfl_xor_sync(0xffffffffu, s1, 1);
        s1 += __shfl_xor_sync(0xffffffffu, s1, 2);
        l0 = l0 * corr0 + s0;
        l1 = l1 * corr1 + s1;

#pragma unroll
        for (int n = 0; n < 8; ++n) {
            acc[n][0] *= corr0; acc[n][1] *= corr0;
            acc[n][2] *= corr1; acc[n][3] *= corr1;
        }

        // PV
#pragma unroll
        for (int kc = 0; kc < 4; ++kc)
#pragma unroll
            for (int n = 0; n < 8; ++n) {
                const int ridx = (n * 8 + g) * 66 + kc * 16 + 2 * t;
                mma_f16(acc[n], aP[kc][0], aP[kc][1], aP[kc][2], aP[kc][3],
                        *(const uint32_t*)&VThs[ridx],
                        *(const uint32_t*)&VThs[ridx + 8]);
            }
    }

    // epilogue
    const float inv0 = 1.0f / l0;
    const float inv1 = 1.0f / l1;
    float* attB = att + (size_t)b * S_ * D_ + h * DK_;
#pragma unroll
    for (int n = 0; n < 8; ++n) {
        const int col = n * 8 + 2 * t;
        float2 o0 = {acc[n][0] * inv0, acc[n][1] * inv0};
        float2 o1 = {acc[n][2] * inv1, acc[n][3] * inv1};
        *(float2*)&attB[(size_t)qr0 * D_ + col] = o0;
        *(float2*)&attB[(size_t)qr1 * D_ + col] = o1;
    }
}

// ---------------------------------------------------------------------------
extern "C" void kernel_launch(void* const* d_in, const int* in_sizes, int n_in,
                              void* d_out, int out_size)
{
    const float* query = (const float*)d_in[0];
    const float* key   = (const float*)d_in[1];
    const float* value = (const float*)d_in[2];
    const int*   mask  = (const int*)  d_in[3];
    const float* gprob = (const float*)d_in[4];
    const float* Wq = (const float*)d_in[5];
    const float* bq = (const float*)d_in[6];
    const float* Wk = (const float*)d_in[7];
    const float* bk = (const float*)d_in[8];
    const float* Wv = (const float*)d_in[9];
    const float* bv = (const float*)d_in[10];
    const float* Wo = (const float*)d_in[11];
    const float* bo = (const float*)d_in[12];
    float* out = (float*)d_out;

    __half *qp, *kp, *vp;
    float* ap;
    cudaGetSymbolAddress((void**)&qp, g_q);
    cudaGetSymbolAddress((void**)&kp, g_k);
    cudaGetSymbolAddress((void**)&vp, g_v);
    cudaGetSymbolAddress((void**)&ap, g_att);

    cudaFuncSetAttribute(qkv_gemm,
                         cudaFuncAttributeMaxDynamicSharedMemorySize, GEMM_SMEM);
    cudaFuncSetAttribute(out_gemm,
                         cudaFuncAttributeMaxDynamicSharedMemorySize, GEMM_SMEM);

    dim3 gqkv(GN / 128, GM / 128, 3);
    qkv_gemm<<<gqkv, 512, GEMM_SMEM>>>(query, key, value,
                                       Wq, Wk, Wv, bq, bk, bv,
                                       qp, kp, vp);

    attn_kernel<<<dim3(S_ / 64, B_ * H_), 128>>>(
        qp, kp, vp, mask, gprob, ap);

    out_gemm<<<dim3(GN / 128, GM / 128), 512, GEMM_SMEM>>>(ap, Wo, bo, out);
}

// round 10
// speedup vs baseline: 4.7034x; 1.0505x over previous
#include <cuda_runtime.h>
#include <cuda_fp16.h>
#include <math.h>
#include <stdint.h>

// Problem constants
#define B_   4
#define S_   1024
#define D_   1024
#define H_   16
#define DK_  64

#define GM   4096
#define GN   1024
#define GK   1024

#define LOG2E 1.4426950408889634f

// fp16 GEMM: 128x128x32 CTA tile, 512 threads, warp tile 32x32,
// cp.async 4-stage ring, ldmatrix fragment loads, fp32 accum.
#define BK_   32
#define SB    40                       // smem row stride in fp16 (80B = 20 banks)
#define PLANE (128 * SB)               // fp16 elems per plane (5120)
#define BUFBYTES (2 * PLANE * 2)       // one stage: A plane + B plane (20480 B)
#define GEMM_SMEM (4 * BUFBYTES)       // 81920 B

// Scratch (allocation-free rule: __device__ globals)
__device__ __half g_x16[3][B_ * S_ * D_];   // query/key/value fp16
__device__ __half g_w16[4][D_ * D_];        // Wq/Wk/Wv/Wo fp16
__device__ __half g_q[B_ * H_ * S_ * DK_];
__device__ __half g_k[B_ * H_ * S_ * DK_];
__device__ __half g_v[B_ * H_ * S_ * DK_];
__device__ __half g_att16[B_ * S_ * D_];

// ---------------------------------------------------------------------------
// helpers
// ---------------------------------------------------------------------------
__device__ __forceinline__ uint32_t smem_u32(const void* p) {
    uint32_t a;
    asm("{ .reg .u64 t; cvta.to.shared.u64 t, %1; cvt.u32.u64 %0, t; }"
        : "=r"(a) : "l"(p));
    return a;
}

// pack two floats into fp16x2 (elem0 -> low half, elem1 -> high half)
__device__ __forceinline__ uint32_t packh2(float e0, float e1) {
    uint32_t r;
    asm("cvt.rn.f16x2.f32 %0, %1, %2;" : "=r"(r) : "f"(e1), "f"(e0));
    return r;
}

__device__ __forceinline__ void mma_f16(
    float c[4], uint32_t a0, uint32_t a1, uint32_t a2, uint32_t a3,
    uint32_t b0, uint32_t b1)
{
    asm volatile(
        "mma.sync.aligned.m16n8k16.row.col.f32.f16.f16.f32 "
        "{%0,%1,%2,%3}, {%4,%5,%6,%7}, {%8,%9}, {%0,%1,%2,%3};\n"
        : "+f"(c[0]), "+f"(c[1]), "+f"(c[2]), "+f"(c[3])
        : "r"(a0), "r"(a1), "r"(a2), "r"(a3), "r"(b0), "r"(b1));
}

__device__ __forceinline__ void ldsm4(
    uint32_t& r0, uint32_t& r1, uint32_t& r2, uint32_t& r3, uint32_t addr)
{
    asm volatile("ldmatrix.sync.aligned.m8n8.x4.shared.b16 {%0,%1,%2,%3}, [%4];"
                 : "=r"(r0), "=r"(r1), "=r"(r2), "=r"(r3) : "r"(addr));
}

#define CP_ASYNC16(dst, src) \
    asm volatile("cp.async.cg.shared.global [%0], [%1], 16;" \
                 :: "r"(dst), "l"(src) : "memory")
#define CP_COMMIT() asm volatile("cp.async.commit_group;" ::: "memory")
#define CP_WAIT2()  asm volatile("cp.async.wait_group 2;" ::: "memory")

// FFMA-only 2^x for x <= 0
__device__ __forceinline__ float fexp2(float x) {
    x = fmaxf(x, -120.f);
    float r = rintf(x);
    float f = x - r;
    float p = 1.3333558146e-3f;
    p = fmaf(p, f, 9.6181291076e-3f);
    p = fmaf(p, f, 5.5504108664e-2f);
    p = fmaf(p, f, 2.4022650696e-1f);
    p = fmaf(p, f, 6.9314718056e-1f);
    p = fmaf(p, f, 1.0f);
    float s = __int_as_float(((int)r + 127) << 23);
    return p * s;
}

// ---------------------------------------------------------------------------
// fp32 -> fp16 conversion (7 tensors, segment per blockIdx.y)
// ---------------------------------------------------------------------------
__global__ __launch_bounds__(256) void cvt_all(
    const float* q, const float* k, const float* v,
    const float* wq, const float* wk, const float* wv, const float* wo,
    __half* x16base, __half* w16base)
{
    const int seg = blockIdx.y;
    const float* src;
    __half* dst;
    int n;
    if (seg < 3) {
        src = seg == 0 ? q : (seg == 1 ? k : v);
        dst = x16base + (size_t)seg * (B_ * S_ * D_);
        n = B_ * S_ * D_;
    } else {
        src = seg == 3 ? wq : (seg == 4 ? wk : (seg == 5 ? wv : wo));
        dst = w16base + (size_t)(seg - 3) * (D_ * D_);
        n = D_ * D_;
    }
    const int i = (blockIdx.x * 256 + threadIdx.x) * 4;
    if (i < n) {
        float4 f = *(const float4*)(src + i);
        uint2 o;
        o.x = packh2(f.x, f.y);
        o.y = packh2(f.z, f.w);
        *(uint2*)(dst + i) = o;
    }
}

// ---------------------------------------------------------------------------
// fp16 GEMM body: out = A @ W^T + bias.  A,W fp16 in global.
// cp.async 4-stage ring, 1 sync per tile.
// mode 0: f32 [M,N].  mode 1: fp16 scatter to [B*H,S,DK], scaled.
// ---------------------------------------------------------------------------
__device__ __forceinline__ void gemm_f16_body(
    const __half* __restrict__ A, const __half* __restrict__ W,
    const float* __restrict__ bias, float* __restrict__ outF,
    __half* __restrict__ outH, float scale, int mode)
{
    extern __shared__ __align__(16) char smemRaw[];
    const uint32_t smb = smem_u32(smemRaw);

    const int tid  = threadIdx.x;
    const int lane = tid & 31;
    const int warp = tid >> 5;
    const int wm   = warp & 3;          // 4 m-warps
    const int wn   = warp >> 2;         // 4 n-warps
    const int g    = lane >> 2;
    const int t    = lane & 3;

    const int m0 = blockIdx.y * 128;
    const int n0 = blockIdx.x * 128;

    // staging: 4 threads per row, 8 halves (16B) each
    const int r  = tid >> 2;            // 0..127
    const int ch = tid & 3;             // 0..3
    const __half* Ap = A + (size_t)(m0 + r) * GK + ch * 8;
    const __half* Wp = W + (size_t)(n0 + r) * GK + ch * 8;
    const uint32_t stOff = (uint32_t)(r * SB + ch * 8) * 2;

    float c[2][4][4];
#pragma unroll
    for (int mi = 0; mi < 2; ++mi)
#pragma unroll
        for (int ni = 0; ni < 4; ++ni)
#pragma unroll
            for (int e = 0; e < 4; ++e) c[mi][ni][e] = 0.f;

    const int KT = GK / BK_;            // 32

    // ldmatrix lane addressing (fp16 element offsets within a plane)
    const int aRowOff = (wm * 32 + (lane & 15)) * SB + (lane >> 4) * 8;
    const int bRowOff = (wn * 32 + (lane & 7) + (lane >> 4) * 8) * SB
                        + ((lane >> 3) & 1) * 8;

    // prologue: issue tiles 0,1,2
#pragma unroll
    for (int pt = 0; pt < 3; ++pt) {
        const uint32_t d = smb + pt * BUFBYTES + stOff;
        CP_ASYNC16(d, Ap + (size_t)pt * BK_);
        CP_ASYNC16(d + PLANE * 2, Wp + (size_t)pt * BK_);
        CP_COMMIT();
    }

    for (int tt = 0; tt < KT; ++tt) {
        CP_WAIT2();
        __syncthreads();
        // issue tile tt+3 into ring slot (tt+3)&3 (the buffer consumed at tt-1)
        if (tt + 3 < KT) {
            const uint32_t d = smb + ((tt + 3) & 3) * BUFBYTES + stOff;
            CP_ASYNC16(d, Ap + (size_t)(tt + 3) * BK_);
            CP_ASYNC16(d + PLANE * 2, Wp + (size_t)(tt + 3) * BK_);
        }
        CP_COMMIT();   // uniform group count (empty group near the end)

        const uint32_t bufB = smb + (tt & 3) * BUFBYTES;
        const uint32_t ah = bufB + 2 * aRowOff;
        const uint32_t bh = bufB + 2 * (PLANE + bRowOff);

#pragma unroll
        for (int kk = 0; kk < BK_; kk += 16) {
            uint32_t Af[2][4], Bf[2][4];
#pragma unroll
            for (int mi = 0; mi < 2; ++mi) {
                const uint32_t ro = 2 * (mi * 16 * SB + kk);
                ldsm4(Af[mi][0], Af[mi][1], Af[mi][2], Af[mi][3], ah + ro);
            }
#pragma unroll
            for (int np = 0; np < 2; ++np) {
                const uint32_t ro = 2 * (np * 16 * SB + kk);
                ldsm4(Bf[np][0], Bf[np][1], Bf[np][2], Bf[np][3], bh + ro);
            }
#pragma unroll
            for (int mi = 0; mi < 2; ++mi)
#pragma unroll
                for (int ni = 0; ni < 4; ++ni) {
                    const int np = ni >> 1, q = (ni & 1) * 2;
                    mma_f16(c[mi][ni], Af[mi][0], Af[mi][1], Af[mi][2], Af[mi][3],
                            Bf[np][q], Bf[np][q + 1]);
                }
        }
    }

    // epilogue
#pragma unroll
    for (int mi = 0; mi < 2; ++mi) {
        const int row0 = m0 + wm * 32 + mi * 16 + g;
        const int row1 = row0 + 8;
#pragma unroll
        for (int ni = 0; ni < 4; ++ni) {
            const int col = n0 + wn * 32 + ni * 8 + t * 2;
            const float b0v = bias[col], b1v = bias[col + 1];
            if (mode == 0) {
                float2 o0 = {c[mi][ni][0] + b0v, c[mi][ni][1] + b1v};
                float2 o1 = {c[mi][ni][2] + b0v, c[mi][ni][3] + b1v};
                *(float2*)&outF[(size_t)row0 * GN + col] = o0;
                *(float2*)&outF[(size_t)row1 * GN + col] = o1;
            } else {
                const int h  = col >> 6, dk = col & (DK_ - 1);
                const int b0r = row0 >> 10, s0 = row0 & (S_ - 1);
                const int b1r = row1 >> 10, s1 = row1 & (S_ - 1);
                const size_t i0 = (((size_t)(b0r * H_ + h)) * S_ + s0) * DK_ + dk;
                const size_t i1 = (((size_t)(b1r * H_ + h)) * S_ + s1) * DK_ + dk;
                *(uint32_t*)&outH[i0] =
                    packh2((c[mi][ni][0] + b0v) * scale, (c[mi][ni][1] + b1v) * scale);
                *(uint32_t*)&outH[i1] =
                    packh2((c[mi][ni][2] + b0v) * scale, (c[mi][ni][3] + b1v) * scale);
            }
        }
    }
}

__global__ __launch_bounds__(512) void qkv_gemm(
    const __half* __restrict__ x16, const __half* __restrict__ w16,
    const float* __restrict__ b0, const float* __restrict__ b1,
    const float* __restrict__ b2,
    __half* q, __half* k, __half* v)
{
    const int z = blockIdx.z;
    const __half* A = x16 + (size_t)z * (B_ * S_ * D_);
    const __half* W = w16 + (size_t)z * (D_ * D_);
    const float* bi = z == 0 ? b0 : (z == 1 ? b1 : b2);
    __half* o = z == 0 ? q : (z == 1 ? k : v);
    const float sc = z == 0 ? 0.125f : 1.f;
    gemm_f16_body(A, W, bi, nullptr, o, sc, 1);
}

__global__ __launch_bounds__(512) void out_gemm(
    const __half* __restrict__ A, const __half* __restrict__ W,
    const float* __restrict__ bias, float* __restrict__ out)
{
    gemm_f16_body(A, W, bias, out, nullptr, 1.f, 0);
}

// ---------------------------------------------------------------------------
// fp16 tensor-core flash attention, 256 threads = 8 warps, q-tile 128 rows.
// Each warp owns 16 q rows. Output written as fp16 (for fp16 out_gemm input).
// ---------------------------------------------------------------------------
__global__ __launch_bounds__(256) void attn_kernel(
    const __half* __restrict__ q, const __half* __restrict__ k,
    const __half* __restrict__ v,
    const int* __restrict__ mask, const float* __restrict__ gp,
    __half* __restrict__ att)
{
    __shared__ __align__(16) uint32_t Khs32[64 * 36];
    __shared__ __align__(16) __half   VThs[64 * 66];

    const int tid  = threadIdx.x;
    const int lane = tid & 31;
    const int warp = tid >> 5;      // 0..7
    const int g    = lane >> 2;
    const int t    = lane & 3;

    const int bh = blockIdx.y;
    const int b  = bh >> 4;
    const int h  = bh & 15;
    const int q0 = blockIdx.x * 128;

    const int qr0 = q0 + warp * 16 + g;
    const int qr1 = qr0 + 8;

    const __half* qB = q + (size_t)bh * S_ * DK_;
    const __half* kB = k + (size_t)bh * S_ * DK_;
    const __half* vB = v + (size_t)bh * S_ * DK_;
    const int*   maskB = mask + (size_t)b * S_ * S_;
    const float* gpB   = gp   + (size_t)b * S_ * S_;

    // Q fragments (held for entire kernel)
    uint32_t aQ[4][4];
#pragma unroll
    for (int kc = 0; kc < 4; ++kc) {
        const int col = kc * 16 + 2 * t;
        aQ[kc][0] = *(const uint32_t*)&qB[qr0 * DK_ + col];
        aQ[kc][1] = *(const uint32_t*)&qB[qr1 * DK_ + col];
        aQ[kc][2] = *(const uint32_t*)&qB[qr0 * DK_ + col + 8];
        aQ[kc][3] = *(const uint32_t*)&qB[qr1 * DK_ + col + 8];
    }

    float acc[8][4];
#pragma unroll
    for (int n = 0; n < 8; ++n)
#pragma unroll
        for (int e = 0; e < 4; ++e) acc[n][e] = 0.f;
    float m0v = -1e30f, m1v = -1e30f, l0 = 0.f, l1 = 0.f;

    for (int kt = 0; kt < S_; kt += 64) {
        __syncthreads();
        // fill K (direct) and V (transposed) tiles; 256 threads, 8 iters
#pragma unroll
        for (int i = 0; i < 8; ++i) {
            const int lin = tid + i * 256;
            const int row = lin >> 5;
            const int cu  = lin & 31;
            Khs32[row * 36 + cu] = *(const uint32_t*)&kB[(kt + row) * DK_ + cu * 2];
            const uint32_t v2 = *(const uint32_t*)&vB[(kt + row) * DK_ + cu * 2];
            VThs[(2 * cu) * 66 + row]     = __ushort_as_half((unsigned short)(v2 & 0xffff));
            VThs[(2 * cu + 1) * 66 + row] = __ushort_as_half((unsigned short)(v2 >> 16));
        }
        __syncthreads();

        // scores
        float cS[8][4];
#pragma unroll
        for (int n = 0; n < 8; ++n)
#pragma unroll
            for (int e = 0; e < 4; ++e) cS[n][e] = 0.f;

#pragma unroll
        for (int kc = 0; kc < 4; ++kc)
#pragma unroll
            for (int n = 0; n < 8; ++n) {
                const int ridx = (n * 8 + g) * 36 + kc * 8 + t;
                mma_f16(cS[n], aQ[kc][0], aQ[kc][1], aQ[kc][2], aQ[kc][3],
                        Khs32[ridx], Khs32[ridx + 4]);
            }

        // mask + gp
        float gpr[8][4];
#pragma unroll
        for (int n = 0; n < 8; ++n) {
            const int kcol = kt + n * 8 + 2 * t;
            const int2   mv0 = *(const int2*)&maskB[(size_t)qr0 * S_ + kcol];
            const int2   mv1 = *(const int2*)&maskB[(size_t)qr1 * S_ + kcol];
            const float2 g0  = *(const float2*)&gpB[(size_t)qr0 * S_ + kcol];
            const float2 g1  = *(const float2*)&gpB[(size_t)qr1 * S_ + kcol];
            cS[n][0] = (mv0.x != 0 || qr0 == kcol)     ? cS[n][0] : -1e9f;
            cS[n][1] = (mv0.y != 0 || qr0 == kcol + 1) ? cS[n][1] : -1e9f;
            cS[n][2] = (mv1.x != 0 || qr1 == kcol)     ? cS[n][2] : -1e9f;
            cS[n][3] = (mv1.y != 0 || qr1 == kcol + 1) ? cS[n][3] : -1e9f;
            gpr[n][0] = g0.x; gpr[n][1] = g0.y; gpr[n][2] = g1.x; gpr[n][3] = g1.y;
        }

        // row max (reduce across t-lanes 1,2)
        float mx0 = -1e30f, mx1 = -1e30f;
#pragma unroll
        for (int n = 0; n < 8; ++n) {
            mx0 = fmaxf(mx0, fmaxf(cS[n][0], cS[n][1]));
            mx1 = fmaxf(mx1, fmaxf(cS[n][2], cS[n][3]));
        }
        mx0 = fmaxf(mx0, __shfl_xor_sync(0xffffffffu, mx0, 1));
        mx0 = fmaxf(mx0, __shfl_xor_sync(0xffffffffu, mx0, 2));
        mx1 = fmaxf(mx1, __shfl_xor_sync(0xffffffffu, mx1, 1));
        mx1 = fmaxf(mx1, __shfl_xor_sync(0xffffffffu, mx1, 2));

        const float nm0 = fmaxf(m0v, mx0);
        const float nm1 = fmaxf(m1v, mx1);
        const float corr0 = fexp2((m0v - nm0) * LOG2E);
        const float corr1 = fexp2((m1v - nm1) * LOG2E);
        m0v = nm0; m1v = nm1;

        // exp + gp, pack P fragments (fp16)
        uint32_t aP[4][4];
        float s0 = 0.f, s1 = 0.f;
#pragma unroll
        for (int n = 0; n < 8; ++n) {
            const float e0 = fexp2((cS[n][0] - nm0) * LOG2E);
            const float e1 = fexp2((cS[n][1] - nm0) * LOG2E);
            const float e2 = fexp2((cS[n][2] - nm1) * LOG2E);
            const float e3 = fexp2((cS[n][3] - nm1) * LOG2E);
            s0 += e0 + e1;
            s1 += e2 + e3;
            const int kc = n >> 1, sl = (n & 1) * 2;
            aP[kc][sl + 0] = packh2(e0 * gpr[n][0], e1 * gpr[n][1]);
            aP[kc][sl + 1] = packh2(e2 * gpr[n][2], e3 * gpr[n][3]);
        }
        s0 += __shfl_xor_sync(0xffffffffu, s0, 1);
        s0 += __shfl_xor_sync(0xffffffffu, s0, 2);
        s1 += __shfl_xor_sync(0xffffffffu, s1, 1);
        s1 += __shfl_xor_sync(0xffffffffu, s1, 2);
        l0 = l0 * corr0 + s0;
        l1 = l1 * corr1 + s1;

#pragma unroll
        for (int n = 0; n < 8; ++n) {
            acc[n][0] *= corr0; acc[n][1] *= corr0;
            acc[n][2] *= corr1; acc[n][3] *= corr1;
        }

        // PV
#pragma unroll
        for (int kc = 0; kc < 4; ++kc)
#pragma unroll
            for (int n = 0; n < 8; ++n) {
                const int ridx = (n * 8 + g) * 66 + kc * 16 + 2 * t;
                mma_f16(acc[n], aP[kc][0], aP[kc][1], aP[kc][2], aP[kc][3],
                        *(const uint32_t*)&VThs[ridx],
                        *(const uint32_t*)&VThs[ridx + 8]);
            }
    }

    // epilogue: divide by softmax denominator, write fp16 [B,S,D]
    const float inv0 = 1.0f / l0;
    const float inv1 = 1.0f / l1;
    __half* attB = att + (size_t)b * S_ * D_ + h * DK_;
#pragma unroll
    for (int n = 0; n < 8; ++n) {
        const int col = n * 8 + 2 * t;
        *(uint32_t*)&attB[(size_t)qr0 * D_ + col] =
            packh2(acc[n][0] * inv0, acc[n][1] * inv0);
        *(uint32_t*)&attB[(size_t)qr1 * D_ + col] =
            packh2(acc[n][2] * inv1, acc[n][3] * inv1);
    }
}

// ---------------------------------------------------------------------------
extern "C" void kernel_launch(void* const* d_in, const int* in_sizes, int n_in,
                              void* d_out, int out_size)
{
    const float* query = (const float*)d_in[0];
    const float* key   = (const float*)d_in[1];
    const float* value = (const float*)d_in[2];
    const int*   mask  = (const int*)  d_in[3];
    const float* gprob = (const float*)d_in[4];
    const float* bq = (const float*)d_in[6];
    const float* bk = (const float*)d_in[8];
    const float* bv = (const float*)d_in[10];
    const float* bo = (const float*)d_in[12];
    float* out = (float*)d_out;

    __half *x16, *w16, *qp, *kp, *vp, *ap;
    cudaGetSymbolAddress((void**)&x16, g_x16);
    cudaGetSymbolAddress((void**)&w16, g_w16);
    cudaGetSymbolAddress((void**)&qp,  g_q);
    cudaGetSymbolAddress((void**)&kp,  g_k);
    cudaGetSymbolAddress((void**)&vp,  g_v);
    cudaGetSymbolAddress((void**)&ap,  g_att16);

    cudaFuncSetAttribute(qkv_gemm,
                         cudaFuncAttributeMaxDynamicSharedMemorySize, GEMM_SMEM);
    cudaFuncSetAttribute(out_gemm,
                         cudaFuncAttributeMaxDynamicSharedMemorySize, GEMM_SMEM);

    // fp32 -> fp16 pre-conversion of activations + weights
    cvt_all<<<dim3((B_ * S_ * D_) / 1024, 7), 256>>>(
        query, key, value,
        (const float*)d_in[5], (const float*)d_in[7],
        (const float*)d_in[9], (const float*)d_in[11],
        x16, w16);

    dim3 gqkv(GN / 128, GM / 128, 3);
    qkv_gemm<<<gqkv, 512, GEMM_SMEM>>>(x16, w16, bq, bk, bv, qp, kp, vp);

    attn_kernel<<<dim3(S_ / 128, B_ * H_), 256>>>(
        qp, kp, vp, mask, gprob, ap);

    out_gemm<<<dim3(GN / 128, GM / 128), 512, GEMM_SMEM>>>(
        ap, w16 + (size_t)3 * D_ * D_, bo, out);
}